// round 7
// baseline (speedup 1.0000x reference)
#include <cuda_runtime.h>
#include <math.h>

#define NN 50000
#define NE 800000
typedef unsigned long long ULL;

// ---------------- device scratch ----------------
__device__ float g_pre1[NN * 64];
__device__ float g_pre2[NN * 64];
__device__ float g_pre3[NN * 64];
__device__ float g_pre4[NN * 64];
// duplicated transposed weights: wd[k*2M + 2m] = wd[k*2M + 2m+1] = w[m*K + k]
__device__ float g_wd0a[128 * 256];
__device__ float g_wd0b[128 * 128];
__device__ float g_wd1a[64 * 128];
__device__ float g_wd1b[64 * 128];
__device__ float g_wd2a[64 * 128];
__device__ float g_wd2b[64 * 128];
__device__ float g_fc1d[320 * 128];
__device__ int   g_cnt[NN];
__device__ int   g_rowptr[NN + 1];
__device__ int   g_cursor[NN];
__device__ int   g_srt[NE];
__device__ int   g_bsum[256];
__device__ int   g_boff[256];
__device__ float g_stats[4 * 128];   // per BN: [0:64) sum, [64:128) sumsq

// ---------------- f32x2 helpers ----------------
__device__ __forceinline__ ULL pk2(float x, float y) {
    ULL r; asm("mov.b64 %0, {%1,%2};" : "=l"(r) : "f"(x), "f"(y)); return r;
}
__device__ __forceinline__ void upk(ULL v, float& x, float& y) {
    asm("mov.b64 {%0,%1}, %2;" : "=f"(x), "=f"(y) : "l"(v));
}
__device__ __forceinline__ void fma2(ULL& d, ULL a, ULL b) {
    asm("fma.rn.f32x2 %0, %1, %2, %0;" : "+l"(d) : "l"(a), "l"(b));
}

// ---------------- launch 1: histogram by dst ----------------
__global__ void hist_kernel(const int* __restrict__ dst, int E) {
    int i = blockIdx.x * blockDim.x + threadIdx.x;
    if (i < E) atomicAdd(&g_cnt[dst[i]], 1);
}

// ---------------- launch 2: partial scan + weight dup-transpose ----------
__global__ void scan_part_prep(int N, int scanBlocks,
                               const float* __restrict__ w0a, const float* __restrict__ w0b,
                               const float* __restrict__ w1a, const float* __restrict__ w1b,
                               const float* __restrict__ w2a, const float* __restrict__ w2b,
                               const float* __restrict__ fc1w) {
    int t = threadIdx.x;
    if ((int)blockIdx.x < scanBlocks) {
        __shared__ int sm[256];
        int idx = blockIdx.x * 256 + t;
        sm[t] = (idx < N) ? g_cnt[idx] : 0;
        __syncthreads();
        for (int o = 128; o; o >>= 1) { if (t < o) sm[t] += sm[t + o]; __syncthreads(); }
        if (t == 0) g_bsum[blockIdx.x] = sm[0];
        return;
    }
    int j = (blockIdx.x - scanBlocks) * 256 + t;
    float v; float* dstp;
    if (j < 16384) { int m = j >> 7, k = j & 127; v = w0a[j]; dstp = &g_wd0a[k * 256 + 2 * m]; }
    else if ((j -= 16384) < 8192) { int m = j >> 7, k = j & 127; v = w0b[j]; dstp = &g_wd0b[k * 128 + 2 * m]; }
    else if ((j -= 8192) < 4096)  { int m = j >> 6, k = j & 63; v = w1a[j]; dstp = &g_wd1a[k * 128 + 2 * m]; }
    else if ((j -= 4096) < 4096)  { int m = j >> 6, k = j & 63; v = w1b[j]; dstp = &g_wd1b[k * 128 + 2 * m]; }
    else if ((j -= 4096) < 4096)  { int m = j >> 6, k = j & 63; v = w2a[j]; dstp = &g_wd2a[k * 128 + 2 * m]; }
    else if ((j -= 4096) < 4096)  { int m = j >> 6, k = j & 63; v = w2b[j]; dstp = &g_wd2b[k * 128 + 2 * m]; }
    else if ((j -= 4096) < 20480) { int m = j / 320, k = j - m * 320; v = fc1w[j]; dstp = &g_fc1d[k * 128 + 2 * m]; }
    else return;
    *(float2*)dstp = make_float2(v, v);
}

// ---------------- launch 3/4: scan top + apply ----------------
__global__ void scan_top(int B) {
    __shared__ int sm[256];
    int t = threadIdx.x;
    sm[t] = (t < B) ? g_bsum[t] : 0;
    __syncthreads();
    for (int o = 1; o < 256; o <<= 1) {
        int u = (t >= o) ? sm[t - o] : 0;
        __syncthreads(); sm[t] += u; __syncthreads();
    }
    g_boff[t] = (t > 0) ? sm[t - 1] : 0;
}
__global__ void scan_apply(int N) {
    __shared__ int sm[256];
    int t = threadIdx.x, idx = blockIdx.x * 256 + t;
    int v = (idx < N) ? g_cnt[idx] : 0;
    sm[t] = v;
    __syncthreads();
    for (int o = 1; o < 256; o <<= 1) {
        int u = (t >= o) ? sm[t - o] : 0;
        __syncthreads(); sm[t] += u; __syncthreads();
    }
    int excl = sm[t] - v + g_boff[blockIdx.x];
    if (idx < N) {
        g_rowptr[idx] = excl;
        g_cursor[idx] = excl;
        if (idx == N - 1) g_rowptr[N] = excl + v;
    }
}

// ---------------- launch 5: scatter + re-zero cnt/stats ----------------
__global__ void scatter_kernel(const int* __restrict__ src, const int* __restrict__ dst, int E, int N) {
    int i = blockIdx.x * blockDim.x + threadIdx.x;
    if (i < E) {
        int p = atomicAdd(&g_cursor[dst[i]], 1);
        g_srt[p] = src[i];
    }
    if (i < N) g_cnt[i] = 0;        // restore invariant for next replay
    if (i < 512) g_stats[i] = 0.f;  // zero BN accumulators before mlp launches
}

// ---------------- launch 6: fused layer 0 (agg from tables + MLP + stats) -
__global__ void __launch_bounds__(256) mlp0_kernel(
    const float* __restrict__ ed, const float* __restrict__ el,
    const int* __restrict__ ndeg, const int* __restrict__ nlab,
    const float* __restrict__ ba, const float* __restrict__ bb,
    float* __restrict__ out, int N)
{
    extern __shared__ float smem[];
    float* A_s = smem;               // 128*66
    float* H_s = smem + 128 * 66;    // 128*66
    float* RS  = H_s + 128 * 66;     // 512
    float* RQ  = RS + 512;           // 512

    const int tid = threadIdx.x;
    const int lane = tid & 31, wrp = tid >> 5;
    const int n0 = blockIdx.x * 64;

    // ---- phase A: gather+sum x0 rows straight from embedding tables ----
    {
        const float* tbl    = (lane < 16) ? ed : el;
        const int*   idxarr = (lane < 16) ? ndeg : nlab;
        const int    offi   = (lane & 15) * 4;
        const int    k0     = (lane < 16) ? lane * 4 : 64 + (lane - 16) * 4;
#pragma unroll
        for (int rep = 0; rep < 8; rep++) {
            int nl = rep * 8 + wrp;
            int n  = n0 + nl;
            float4 acc = make_float4(0.f, 0.f, 0.f, 0.f);
            if (n < N) {
                acc = *(const float4*)&tbl[idxarr[n] * 64 + offi];
                int e = g_rowptr[n], end = g_rowptr[n + 1];
                for (; e + 4 <= end; e += 4) {
                    int s0 = g_srt[e], s1 = g_srt[e + 1], s2 = g_srt[e + 2], s3 = g_srt[e + 3];
                    int i0 = idxarr[s0], i1 = idxarr[s1], i2 = idxarr[s2], i3 = idxarr[s3];
                    float4 v0 = *(const float4*)&tbl[i0 * 64 + offi];
                    float4 v1 = *(const float4*)&tbl[i1 * 64 + offi];
                    float4 v2 = *(const float4*)&tbl[i2 * 64 + offi];
                    float4 v3 = *(const float4*)&tbl[i3 * 64 + offi];
                    acc.x += (v0.x + v1.x) + (v2.x + v3.x);
                    acc.y += (v0.y + v1.y) + (v2.y + v3.y);
                    acc.z += (v0.z + v1.z) + (v2.z + v3.z);
                    acc.w += (v0.w + v1.w) + (v2.w + v3.w);
                }
                for (; e < end; e++) {
                    float4 v = *(const float4*)&tbl[idxarr[g_srt[e]] * 64 + offi];
                    acc.x += v.x; acc.y += v.y; acc.z += v.z; acc.w += v.w;
                }
            }
            A_s[(k0 + 0) * 66 + nl] = acc.x;
            A_s[(k0 + 1) * 66 + nl] = acc.y;
            A_s[(k0 + 2) * 66 + nl] = acc.z;
            A_s[(k0 + 3) * 66 + nl] = acc.w;
        }
    }
    __syncthreads();

    const int nb = wrp * 8;
    // ---- GEMM1: [64n x 128k] @ [128k x 128m] ----
    ULL acc[4][4];
#pragma unroll
    for (int i = 0; i < 4; i++)
#pragma unroll
        for (int p = 0; p < 4; p++) acc[i][p] = 0ULL;

#pragma unroll 8
    for (int k = 0; k < 128; k++) {
        const float* row = &A_s[k * 66 + nb];
        ULL a0 = *(const ULL*)(row + 0);
        ULL a1 = *(const ULL*)(row + 2);
        ULL a2 = *(const ULL*)(row + 4);
        ULL a3 = *(const ULL*)(row + 6);
        ulonglong2 q0 = *(const ulonglong2*)&g_wd0a[k * 256 + lane * 8];
        ulonglong2 q1 = *(const ulonglong2*)&g_wd0a[k * 256 + lane * 8 + 4];
        fma2(acc[0][0], q0.x, a0); fma2(acc[0][1], q0.x, a1); fma2(acc[0][2], q0.x, a2); fma2(acc[0][3], q0.x, a3);
        fma2(acc[1][0], q0.y, a0); fma2(acc[1][1], q0.y, a1); fma2(acc[1][2], q0.y, a2); fma2(acc[1][3], q0.y, a3);
        fma2(acc[2][0], q1.x, a0); fma2(acc[2][1], q1.x, a1); fma2(acc[2][2], q1.x, a2); fma2(acc[2][3], q1.x, a3);
        fma2(acc[3][0], q1.y, a0); fma2(acc[3][1], q1.y, a1); fma2(acc[3][2], q1.y, a2); fma2(acc[3][3], q1.y, a3);
    }
#pragma unroll
    for (int i = 0; i < 4; i++) {
        int m = lane * 4 + i;
        float bv = ba[m];
#pragma unroll
        for (int p = 0; p < 4; p++) {
            float x, y; upk(acc[i][p], x, y);
            x += bv; y += bv;
            x = fmaxf(x, 0.01f * x); y = fmaxf(y, 0.01f * y);
            *(ULL*)&H_s[m * 66 + nb + 2 * p] = pk2(x, y);
        }
    }
    __syncthreads();

    // ---- GEMM2: [64n x 128k] @ [128k x 64m] ----
    ULL c2[2][4];
#pragma unroll
    for (int i = 0; i < 2; i++)
#pragma unroll
        for (int p = 0; p < 4; p++) c2[i][p] = 0ULL;
#pragma unroll 8
    for (int k = 0; k < 128; k++) {
        const float* row = &H_s[k * 66 + nb];
        ULL a0 = *(const ULL*)(row + 0);
        ULL a1 = *(const ULL*)(row + 2);
        ULL a2 = *(const ULL*)(row + 4);
        ULL a3 = *(const ULL*)(row + 6);
        ulonglong2 q = *(const ulonglong2*)&g_wd0b[k * 128 + lane * 4];
        fma2(c2[0][0], q.x, a0); fma2(c2[0][1], q.x, a1); fma2(c2[0][2], q.x, a2); fma2(c2[0][3], q.x, a3);
        fma2(c2[1][0], q.y, a0); fma2(c2[1][1], q.y, a1); fma2(c2[1][2], q.y, a2); fma2(c2[1][3], q.y, a3);
    }
    float b0 = bb[lane * 2], b1 = bb[lane * 2 + 1];
    float s0 = 0.f, q0 = 0.f, s1 = 0.f, q1 = 0.f;
#pragma unroll
    for (int p = 0; p < 4; p++) {
        float x0, x1, y0, y1;
        upk(c2[0][p], x0, x1);
        upk(c2[1][p], y0, y1);
        int na = n0 + nb + 2 * p;
        if (na < N) {
            float o0 = x0 + b0, o1 = y0 + b1;
            *(float2*)&out[na * 64 + lane * 2] = make_float2(o0, o1);
            s0 += o0; q0 = fmaf(o0, o0, q0); s1 += o1; q1 = fmaf(o1, o1, q1);
        }
        if (na + 1 < N) {
            float o0 = x1 + b0, o1 = y1 + b1;
            *(float2*)&out[(na + 1) * 64 + lane * 2] = make_float2(o0, o1);
            s0 += o0; q0 = fmaf(o0, o0, q0); s1 += o1; q1 = fmaf(o1, o1, q1);
        }
    }
    RS[wrp * 64 + lane * 2] = s0; RS[wrp * 64 + lane * 2 + 1] = s1;
    RQ[wrp * 64 + lane * 2] = q0; RQ[wrp * 64 + lane * 2 + 1] = q1;
    __syncthreads();
    if (tid < 128) {
        int c = tid & 63;
        const float* P = (tid >= 64) ? RQ : RS;
        float v = 0.f;
#pragma unroll
        for (int w = 0; w < 8; w++) v += P[w * 64 + c];
        atomicAdd(&g_stats[((tid >= 64) ? 64 : 0) + c], v);
    }
}

// ---------------- launches 7/8: fused layers 1/2 ----------------
__global__ void __launch_bounds__(256) mlp12_kernel(
    const float* __restrict__ pre,
    const float* __restrict__ bnw, const float* __restrict__ bnb,
    const float* __restrict__ wda, const float* __restrict__ ba,
    const float* __restrict__ wdb, const float* __restrict__ bb,
    float* __restrict__ out, int N, int bnin, int bnout)
{
    extern __shared__ float smem[];
    float* A_s = smem;               // 64*66
    float* H_s = smem + 64 * 66;     // 64*66
    float* RS  = H_s + 64 * 66;      // 512
    float* RQ  = RS + 512;           // 512
    float* sc  = RQ + 512;           // 64
    float* sh  = sc + 64;            // 64

    const int tid = threadIdx.x;
    const int lane = tid & 31, wrp = tid >> 5;
    const int n0 = blockIdx.x * 64;

    if (tid < 64) {
        int c = tid;
        float m   = g_stats[bnin * 128 + c] / (float)N;
        float var = g_stats[bnin * 128 + 64 + c] / (float)N - m * m;
        float inv = rsqrtf(var + 1e-5f);
        float a   = bnw[c] * inv;
        sc[c] = a;
        sh[c] = bnb[c] - m * a;
    }
    __syncthreads();

    // ---- phase A: gather+sum BN(lrelu(pre)) rows ----
    {
        const int k0 = lane * 2;
        const float a0 = sc[k0], a1 = sc[k0 + 1];
        const float c0 = sh[k0], c1 = sh[k0 + 1];
#define BNR(v) { v.x = fmaf(v.x, a0, c0); v.x = fmaxf(v.x, 0.01f * v.x); \
                 v.y = fmaf(v.y, a1, c1); v.y = fmaxf(v.y, 0.01f * v.y); }
#pragma unroll
        for (int rep = 0; rep < 8; rep++) {
            int nl = rep * 8 + wrp;
            int n  = n0 + nl;
            float2 acc = make_float2(0.f, 0.f);
            if (n < N) {
                acc = *(const float2*)&pre[n * 64 + k0];
                BNR(acc);
                int e = g_rowptr[n], end = g_rowptr[n + 1];
                for (; e + 4 <= end; e += 4) {
                    int s0 = g_srt[e], s1 = g_srt[e + 1], s2 = g_srt[e + 2], s3 = g_srt[e + 3];
                    float2 v0 = *(const float2*)&pre[s0 * 64 + k0];
                    float2 v1 = *(const float2*)&pre[s1 * 64 + k0];
                    float2 v2 = *(const float2*)&pre[s2 * 64 + k0];
                    float2 v3 = *(const float2*)&pre[s3 * 64 + k0];
                    BNR(v0); BNR(v1); BNR(v2); BNR(v3);
                    acc.x += (v0.x + v1.x) + (v2.x + v3.x);
                    acc.y += (v0.y + v1.y) + (v2.y + v3.y);
                }
                for (; e < end; e++) {
                    float2 v = *(const float2*)&pre[g_srt[e] * 64 + k0];
                    BNR(v);
                    acc.x += v.x; acc.y += v.y;
                }
            }
            A_s[(k0 + 0) * 66 + nl] = acc.x;
            A_s[(k0 + 1) * 66 + nl] = acc.y;
        }
#undef BNR
    }
    __syncthreads();

    const int nb = wrp * 8;
    // ---- GEMM1: K=64 -> M=64 ----
    ULL acc[2][4];
#pragma unroll
    for (int i = 0; i < 2; i++)
#pragma unroll
        for (int p = 0; p < 4; p++) acc[i][p] = 0ULL;
#pragma unroll 8
    for (int k = 0; k < 64; k++) {
        const float* row = &A_s[k * 66 + nb];
        ULL a0 = *(const ULL*)(row + 0);
        ULL a1 = *(const ULL*)(row + 2);
        ULL a2 = *(const ULL*)(row + 4);
        ULL a3 = *(const ULL*)(row + 6);
        ulonglong2 q = *(const ulonglong2*)&wda[k * 128 + lane * 4];
        fma2(acc[0][0], q.x, a0); fma2(acc[0][1], q.x, a1); fma2(acc[0][2], q.x, a2); fma2(acc[0][3], q.x, a3);
        fma2(acc[1][0], q.y, a0); fma2(acc[1][1], q.y, a1); fma2(acc[1][2], q.y, a2); fma2(acc[1][3], q.y, a3);
    }
#pragma unroll
    for (int i = 0; i < 2; i++) {
        int m = lane * 2 + i;
        float bv = ba[m];
#pragma unroll
        for (int p = 0; p < 4; p++) {
            float x, y; upk(acc[i][p], x, y);
            x += bv; y += bv;
            x = fmaxf(x, 0.01f * x); y = fmaxf(y, 0.01f * y);
            *(ULL*)&H_s[m * 66 + nb + 2 * p] = pk2(x, y);
        }
    }
    __syncthreads();

    // ---- GEMM2: K=64 -> M=64 ----
    ULL c2[2][4];
#pragma unroll
    for (int i = 0; i < 2; i++)
#pragma unroll
        for (int p = 0; p < 4; p++) c2[i][p] = 0ULL;
#pragma unroll 8
    for (int k = 0; k < 64; k++) {
        const float* row = &H_s[k * 66 + nb];
        ULL a0 = *(const ULL*)(row + 0);
        ULL a1 = *(const ULL*)(row + 2);
        ULL a2 = *(const ULL*)(row + 4);
        ULL a3 = *(const ULL*)(row + 6);
        ulonglong2 q = *(const ulonglong2*)&wdb[k * 128 + lane * 4];
        fma2(c2[0][0], q.x, a0); fma2(c2[0][1], q.x, a1); fma2(c2[0][2], q.x, a2); fma2(c2[0][3], q.x, a3);
        fma2(c2[1][0], q.y, a0); fma2(c2[1][1], q.y, a1); fma2(c2[1][2], q.y, a2); fma2(c2[1][3], q.y, a3);
    }
    float b0 = bb[lane * 2], b1 = bb[lane * 2 + 1];
    float s0 = 0.f, q0 = 0.f, s1 = 0.f, q1 = 0.f;
#pragma unroll
    for (int p = 0; p < 4; p++) {
        float x0, x1, y0, y1;
        upk(c2[0][p], x0, x1);
        upk(c2[1][p], y0, y1);
        int na = n0 + nb + 2 * p;
        if (na < N) {
            float o0 = x0 + b0, o1 = y0 + b1;
            *(float2*)&out[na * 64 + lane * 2] = make_float2(o0, o1);
            s0 += o0; q0 = fmaf(o0, o0, q0); s1 += o1; q1 = fmaf(o1, o1, q1);
        }
        if (na + 1 < N) {
            float o0 = x1 + b0, o1 = y1 + b1;
            *(float2*)&out[(na + 1) * 64 + lane * 2] = make_float2(o0, o1);
            s0 += o0; q0 = fmaf(o0, o0, q0); s1 += o1; q1 = fmaf(o1, o1, q1);
        }
    }
    RS[wrp * 64 + lane * 2] = s0; RS[wrp * 64 + lane * 2 + 1] = s1;
    RQ[wrp * 64 + lane * 2] = q0; RQ[wrp * 64 + lane * 2 + 1] = q1;
    __syncthreads();
    if (tid < 128) {
        int c = tid & 63;
        const float* P = (tid >= 64) ? RQ : RS;
        float v = 0.f;
#pragma unroll
        for (int w = 0; w < 8; w++) v += P[w * 64 + c];
        atomicAdd(&g_stats[bnout * 128 + ((tid >= 64) ? 64 : 0) + c], v);
    }
}

// ---------------- launch 9: fc1 head GEMM (K=320) ----------------
__global__ void __launch_bounds__(256) fc1_kernel(
    const float* __restrict__ ed, const float* __restrict__ el,
    const int* __restrict__ ndeg, const int* __restrict__ nlab,
    const float* __restrict__ pre1, const float* __restrict__ pre2, const float* __restrict__ pre3,
    const float* __restrict__ bn0w, const float* __restrict__ bn0b,
    const float* __restrict__ bn1w, const float* __restrict__ bn1b,
    const float* __restrict__ bn2w, const float* __restrict__ bn2b,
    const float* __restrict__ fb,
    float* __restrict__ out, int N)
{
    extern __shared__ float smem[];
    float* A_s = smem;                 // 320*66 = 21120
    float* RS  = A_s + 21120;          // 512
    float* RQ  = RS + 512;             // 512
    float* sc  = RQ + 512;             // 192
    float* sh  = sc + 192;             // 192

    const int tid = threadIdx.x;
    if (tid < 192) {
        int l = tid >> 6, c = tid & 63;
        const float* w = (l == 0) ? bn0w : ((l == 1) ? bn1w : bn2w);
        const float* b = (l == 0) ? bn0b : ((l == 1) ? bn1b : bn2b);
        float m   = g_stats[l * 128 + c] / (float)N;
        float var = g_stats[l * 128 + 64 + c] / (float)N - m * m;
        float inv = rsqrtf(var + 1e-5f);
        float a   = w[c] * inv;
        sc[tid] = a;
        sh[tid] = b[c] - m * a;
    }
    __syncthreads();

    const int n0 = blockIdx.x * 64;
    for (int i = tid; i < 64 * 320; i += 256) {
        int nl = i / 320, k = i - nl * 320;
        int n = n0 + nl;
        float v = 0.f;
        if (n < N) {
            if (k < 64)       v = ed[ndeg[n] * 64 + k];
            else if (k < 128) v = el[nlab[n] * 64 + (k - 64)];
            else {
                int l = (k - 128) >> 6, c = (k - 128) & 63;
                const float* pr = (l == 0) ? pre1 : ((l == 1) ? pre2 : pre3);
                float p = fmaf(pr[n * 64 + c], sc[l * 64 + c], sh[l * 64 + c]);
                v = fmaxf(p, 0.01f * p);
            }
        }
        A_s[k * 66 + nl] = v;
    }
    __syncthreads();

    const int lane = tid & 31, wrp = tid >> 5;
    const int nb = wrp * 8;

    ULL c2[2][4];
#pragma unroll
    for (int i = 0; i < 2; i++)
#pragma unroll
        for (int p = 0; p < 4; p++) c2[i][p] = 0ULL;

#pragma unroll 8
    for (int k = 0; k < 320; k++) {
        const float* row = &A_s[k * 66 + nb];
        ULL a0 = *(const ULL*)(row + 0);
        ULL a1 = *(const ULL*)(row + 2);
        ULL a2 = *(const ULL*)(row + 4);
        ULL a3 = *(const ULL*)(row + 6);
        ulonglong2 q = *(const ulonglong2*)&g_fc1d[k * 128 + lane * 4];
        fma2(c2[0][0], q.x, a0); fma2(c2[0][1], q.x, a1); fma2(c2[0][2], q.x, a2); fma2(c2[0][3], q.x, a3);
        fma2(c2[1][0], q.y, a0); fma2(c2[1][1], q.y, a1); fma2(c2[1][2], q.y, a2); fma2(c2[1][3], q.y, a3);
    }

    float b0 = fb[lane * 2], b1 = fb[lane * 2 + 1];
    float s0 = 0.f, q0 = 0.f, s1 = 0.f, q1 = 0.f;
#pragma unroll
    for (int p = 0; p < 4; p++) {
        float x0, x1, y0, y1;
        upk(c2[0][p], x0, x1);
        upk(c2[1][p], y0, y1);
        int na = n0 + nb + 2 * p;
        if (na < N) {
            float o0 = x0 + b0, o1 = y0 + b1;
            *(float2*)&out[na * 64 + lane * 2] = make_float2(o0, o1);
            s0 += o0; q0 = fmaf(o0, o0, q0); s1 += o1; q1 = fmaf(o1, o1, q1);
        }
        if (na + 1 < N) {
            float o0 = x1 + b0, o1 = y1 + b1;
            *(float2*)&out[(na + 1) * 64 + lane * 2] = make_float2(o0, o1);
            s0 += o0; q0 = fmaf(o0, o0, q0); s1 += o1; q1 = fmaf(o1, o1, q1);
        }
    }
    RS[wrp * 64 + lane * 2] = s0; RS[wrp * 64 + lane * 2 + 1] = s1;
    RQ[wrp * 64 + lane * 2] = q0; RQ[wrp * 64 + lane * 2 + 1] = q1;
    __syncthreads();
    if (tid < 128) {
        int c = tid & 63;
        const float* P = (tid >= 64) ? RQ : RS;
        float v = 0.f;
#pragma unroll
        for (int w = 0; w < 8; w++) v += P[w * 64 + c];
        atomicAdd(&g_stats[3 * 128 + ((tid >= 64) ? 64 : 0) + c], v);
    }
}

// ---------------- launch 10: final head ----------------
__global__ void final_kernel(const float* __restrict__ hpre,
                             const float* __restrict__ bnw, const float* __restrict__ bnb,
                             const float* __restrict__ fc2w, const float* __restrict__ fc2b,
                             float* __restrict__ out, int N) {
    __shared__ float sc[64], sh[64], w2s[64];
    if (threadIdx.x < 64) {
        int c = threadIdx.x;
        float m   = g_stats[3 * 128 + c] / (float)N;
        float var = g_stats[3 * 128 + 64 + c] / (float)N - m * m;
        float inv = rsqrtf(var + 1e-5f);
        float a   = bnw[c] * inv;
        sc[c]  = a;
        sh[c]  = bnb[c] - m * a;
        w2s[c] = fc2w[c];
    }
    __syncthreads();
    int wid  = (blockIdx.x * blockDim.x + threadIdx.x) >> 5;
    int lane = threadIdx.x & 31;
    if (wid >= N) return;
    float2 v = *(const float2*)&hpre[wid * 64 + lane * 2];
    float x = fmaf(v.x, sc[lane * 2], sh[lane * 2]);         x = fmaxf(x, 0.01f * x);
    float y = fmaf(v.y, sc[lane * 2 + 1], sh[lane * 2 + 1]); y = fmaxf(y, 0.01f * y);
    float acc = fmaf(x, w2s[lane * 2], y * w2s[lane * 2 + 1]);
#pragma unroll
    for (int off = 16; off; off >>= 1) acc += __shfl_xor_sync(0xffffffffu, acc, off);
    if (lane == 0) out[wid] = 1.f / (1.f + expf(-(acc + fc2b[0])));
}

// ---------------- launch ----------------
extern "C" void kernel_launch(void* const* d_in, const int* in_sizes, int n_in,
                              void* d_out, int out_size) {
    const float* emb_deg = (const float*)d_in[0];
    const float* emb_lab = (const float*)d_in[1];
    const float* w0a = (const float*)d_in[2];  const float* b0a = (const float*)d_in[3];
    const float* w0b = (const float*)d_in[4];  const float* b0b = (const float*)d_in[5];
    const float* bn0w = (const float*)d_in[6]; const float* bn0b = (const float*)d_in[7];
    const float* w1a = (const float*)d_in[8];  const float* b1a = (const float*)d_in[9];
    const float* w1b = (const float*)d_in[10]; const float* b1b = (const float*)d_in[11];
    const float* bn1w = (const float*)d_in[12]; const float* bn1b = (const float*)d_in[13];
    const float* w2a = (const float*)d_in[14]; const float* b2a = (const float*)d_in[15];
    const float* w2b = (const float*)d_in[16]; const float* b2b = (const float*)d_in[17];
    const float* bn2w = (const float*)d_in[18]; const float* bn2b = (const float*)d_in[19];
    const float* fc1w = (const float*)d_in[20]; const float* fc1b = (const float*)d_in[21];
    const float* fcbnw = (const float*)d_in[22]; const float* fcbnb = (const float*)d_in[23];
    const float* fc2w = (const float*)d_in[24]; const float* fc2b = (const float*)d_in[25];
    const int* node_deg = (const int*)d_in[26];
    const int* node_lab = (const int*)d_in[27];
    const int* edge = (const int*)d_in[28];

    const int N = in_sizes[26];
    const int E = in_sizes[28] / 2;
    const int* src  = edge;
    const int* dstp = edge + E;
    float* out = (float*)d_out;

    float *pre1, *pre2, *pre3, *pre4, *wd1a, *wd1b, *wd2a, *wd2b;
    cudaGetSymbolAddress((void**)&pre1, g_pre1);
    cudaGetSymbolAddress((void**)&pre2, g_pre2);
    cudaGetSymbolAddress((void**)&pre3, g_pre3);
    cudaGetSymbolAddress((void**)&pre4, g_pre4);
    cudaGetSymbolAddress((void**)&wd1a, g_wd1a);
    cudaGetSymbolAddress((void**)&wd1b, g_wd1b);
    cudaGetSymbolAddress((void**)&wd2a, g_wd2a);
    cudaGetSymbolAddress((void**)&wd2b, g_wd2b);

    const int TB = 256;
    const int mlpBlocks  = (N + 63) / 64;
    const int warpBlocks = (N * 32 + TB - 1) / TB;
    const int scanBlocks = (N + 255) / 256;
    const int prepBlocks = (61440 + 255) / 256;

    const int SM_MLP0 = (128 * 66 * 2 + 1024) * 4;            // 71680
    const int SM_MLP1 = (64 * 66 * 2 + 1024 + 128) * 4;       // 38400
    const int SM_FC1  = (21120 + 1024 + 384) * 4;             // 90112
    cudaFuncSetAttribute(mlp0_kernel,  cudaFuncAttributeMaxDynamicSharedMemorySize, SM_MLP0);
    cudaFuncSetAttribute(mlp12_kernel, cudaFuncAttributeMaxDynamicSharedMemorySize, SM_MLP1);
    cudaFuncSetAttribute(fc1_kernel,   cudaFuncAttributeMaxDynamicSharedMemorySize, SM_FC1);

    // 1: histogram (g_cnt is zero: static-init on first call, re-zeroed by scatter afterwards)
    hist_kernel<<<(E + TB - 1) / TB, TB>>>(dstp, E);
    // 2: partial scan + weight dup-transpose
    scan_part_prep<<<scanBlocks + prepBlocks, 256>>>(N, scanBlocks, w0a, w0b, w1a, w1b, w2a, w2b, fc1w);
    // 3-4: scan
    scan_top<<<1, 256>>>(scanBlocks);
    scan_apply<<<scanBlocks, 256>>>(N);
    // 5: scatter + re-zero cnt/stats
    scatter_kernel<<<(E + TB - 1) / TB, TB>>>(src, dstp, E, N);
    // 6: fused layer 0 (profiled by ncu -s 5 -c 1)
    mlp0_kernel<<<mlpBlocks, 256, SM_MLP0>>>(emb_deg, emb_lab, node_deg, node_lab, b0a, b0b, pre1, N);
    // 7-8: fused layers 1/2
    mlp12_kernel<<<mlpBlocks, 256, SM_MLP1>>>(pre1, bn0w, bn0b, wd1a, b1a, wd1b, b1b, pre2, N, 0, 1);
    mlp12_kernel<<<mlpBlocks, 256, SM_MLP1>>>(pre2, bn1w, bn1b, wd2a, b2a, wd2b, b2b, pre3, N, 1, 2);
    // 9: head GEMM
    fc1_kernel<<<mlpBlocks, 256, SM_FC1>>>(emb_deg, emb_lab, node_deg, node_lab,
                                           pre1, pre2, pre3,
                                           bn0w, bn0b, bn1w, bn1b, bn2w, bn2b,
                                           fc1b, pre4, N);
    // 10: final head
    final_kernel<<<warpBlocks, TB>>>(pre4, fcbnw, fcbnb, fc2w, fc2b, out, N);
}

// round 8
// speedup vs baseline: 1.0593x; 1.0593x over previous
#include <cuda_runtime.h>
#include <math.h>

#define NN 50000
#define NE 800000
typedef unsigned long long ULL;

// ---------------- device scratch ----------------
__device__ float g_hin [NN * 128];
__device__ float g_pre1[NN * 64];
__device__ float g_pre2[NN * 64];
__device__ float g_pre3[NN * 64];
__device__ float g_pre4[NN * 64];
// duplicated transposed weights: wd[k*2M + 2m] = wd[k*2M + 2m+1] = w[m*K + k]
__device__ float g_wd0a[128 * 256];
__device__ float g_wd0b[128 * 128];
__device__ float g_wd1a[64 * 128];
__device__ float g_wd1b[64 * 128];
__device__ float g_wd2a[64 * 128];
__device__ float g_wd2b[64 * 128];
__device__ float g_fc1d[320 * 128];
__device__ int   g_cnt[NN];
__device__ int   g_rowptr[NN + 1];
__device__ int   g_cursor[NN];
__device__ int   g_srt[NE];
__device__ int   g_bsum[256];
__device__ int   g_boff[256];
__device__ float g_stats[4 * 128];   // per BN: [0:64) sum, [64:128) sumsq

// ---------------- f32x2 helpers ----------------
__device__ __forceinline__ ULL pk2(float x, float y) {
    ULL r; asm("mov.b64 %0, {%1,%2};" : "=l"(r) : "f"(x), "f"(y)); return r;
}
__device__ __forceinline__ void upk(ULL v, float& x, float& y) {
    asm("mov.b64 {%0,%1}, %2;" : "=f"(x), "=f"(y) : "l"(v));
}
__device__ __forceinline__ void fma2(ULL& d, ULL a, ULL b) {
    asm("fma.rn.f32x2 %0, %1, %2, %0;" : "+l"(d) : "l"(a), "l"(b));
}

// ---------------- launch 1: histogram by dst ----------------
__global__ void hist_kernel(const int* __restrict__ dst, int E) {
    int i = blockIdx.x * blockDim.x + threadIdx.x;
    if (i < E) atomicAdd(&g_cnt[dst[i]], 1);
}

// ---------------- launch 2: partial scan + weight dup-transpose ----------
__global__ void scan_part_prep(int N, int scanBlocks,
                               const float* __restrict__ w0a, const float* __restrict__ w0b,
                               const float* __restrict__ w1a, const float* __restrict__ w1b,
                               const float* __restrict__ w2a, const float* __restrict__ w2b,
                               const float* __restrict__ fc1w) {
    int t = threadIdx.x;
    if ((int)blockIdx.x < scanBlocks) {
        __shared__ int sm[256];
        int idx = blockIdx.x * 256 + t;
        sm[t] = (idx < N) ? g_cnt[idx] : 0;
        __syncthreads();
        for (int o = 128; o; o >>= 1) { if (t < o) sm[t] += sm[t + o]; __syncthreads(); }
        if (t == 0) g_bsum[blockIdx.x] = sm[0];
        return;
    }
    int j = (blockIdx.x - scanBlocks) * 256 + t;
    float v; float* dstp;
    if (j < 16384) { int m = j >> 7, k = j & 127; v = w0a[j]; dstp = &g_wd0a[k * 256 + 2 * m]; }
    else if ((j -= 16384) < 8192) { int m = j >> 7, k = j & 127; v = w0b[j]; dstp = &g_wd0b[k * 128 + 2 * m]; }
    else if ((j -= 8192) < 4096)  { int m = j >> 6, k = j & 63; v = w1a[j]; dstp = &g_wd1a[k * 128 + 2 * m]; }
    else if ((j -= 4096) < 4096)  { int m = j >> 6, k = j & 63; v = w1b[j]; dstp = &g_wd1b[k * 128 + 2 * m]; }
    else if ((j -= 4096) < 4096)  { int m = j >> 6, k = j & 63; v = w2a[j]; dstp = &g_wd2a[k * 128 + 2 * m]; }
    else if ((j -= 4096) < 4096)  { int m = j >> 6, k = j & 63; v = w2b[j]; dstp = &g_wd2b[k * 128 + 2 * m]; }
    else if ((j -= 4096) < 20480) { int m = j / 320, k = j - m * 320; v = fc1w[j]; dstp = &g_fc1d[k * 128 + 2 * m]; }
    else return;
    *(float2*)dstp = make_float2(v, v);
}

// ---------------- launch 3/4: scan top + apply ----------------
__global__ void scan_top(int B) {
    __shared__ int sm[256];
    int t = threadIdx.x;
    sm[t] = (t < B) ? g_bsum[t] : 0;
    __syncthreads();
    for (int o = 1; o < 256; o <<= 1) {
        int u = (t >= o) ? sm[t - o] : 0;
        __syncthreads(); sm[t] += u; __syncthreads();
    }
    g_boff[t] = (t > 0) ? sm[t - 1] : 0;
}
__global__ void scan_apply(int N) {
    __shared__ int sm[256];
    int t = threadIdx.x, idx = blockIdx.x * 256 + t;
    int v = (idx < N) ? g_cnt[idx] : 0;
    sm[t] = v;
    __syncthreads();
    for (int o = 1; o < 256; o <<= 1) {
        int u = (t >= o) ? sm[t - o] : 0;
        __syncthreads(); sm[t] += u; __syncthreads();
    }
    int excl = sm[t] - v + g_boff[blockIdx.x];
    if (idx < N) {
        g_rowptr[idx] = excl;
        g_cursor[idx] = excl;
        if (idx == N - 1) g_rowptr[N] = excl + v;
    }
}

// ---------------- launch 5: scatter + re-zero cnt/stats ----------------
__global__ void scatter_kernel(const int* __restrict__ src, const int* __restrict__ dst, int E, int N) {
    int i = blockIdx.x * blockDim.x + threadIdx.x;
    if (i < E) {
        int p = atomicAdd(&g_cursor[dst[i]], 1);
        g_srt[p] = src[i];
    }
    if (i < N) g_cnt[i] = 0;        // restore invariant for next replay
    if (i < 512) g_stats[i] = 0.f;  // zero BN accumulators before mlp launches
}

// ---------------- launch 6: layer-0 aggregation from L1-resident tables ---
__global__ void agg0_kernel(const float* __restrict__ ed, const float* __restrict__ el,
                            const int* __restrict__ ndeg, const int* __restrict__ nlab,
                            float* __restrict__ hout, int N) {
    int wid  = (blockIdx.x * blockDim.x + threadIdx.x) >> 5;
    int lane = threadIdx.x & 31;
    if (wid >= N) return;
    const float* tbl    = (lane < 16) ? ed : el;
    const int*   idxarr = (lane < 16) ? ndeg : nlab;
    const int    offi   = (lane & 15) * 4;

    float4 acc = *(const float4*)&tbl[idxarr[wid] * 64 + offi];
    int beg = g_rowptr[wid], end = g_rowptr[wid + 1];
    int e = beg;
    for (; e + 4 <= end; e += 4) {
        int s0 = g_srt[e], s1 = g_srt[e + 1], s2 = g_srt[e + 2], s3 = g_srt[e + 3];
        int i0 = idxarr[s0], i1 = idxarr[s1], i2 = idxarr[s2], i3 = idxarr[s3];
        float4 v0 = *(const float4*)&tbl[i0 * 64 + offi];
        float4 v1 = *(const float4*)&tbl[i1 * 64 + offi];
        float4 v2 = *(const float4*)&tbl[i2 * 64 + offi];
        float4 v3 = *(const float4*)&tbl[i3 * 64 + offi];
        acc.x += (v0.x + v1.x) + (v2.x + v3.x);
        acc.y += (v0.y + v1.y) + (v2.y + v3.y);
        acc.z += (v0.z + v1.z) + (v2.z + v3.z);
        acc.w += (v0.w + v1.w) + (v2.w + v3.w);
    }
    for (; e < end; e++) {
        float4 v = *(const float4*)&tbl[idxarr[g_srt[e]] * 64 + offi];
        acc.x += v.x; acc.y += v.y; acc.z += v.z; acc.w += v.w;
    }
    *(float4*)&hout[wid * 128 + lane * 4] = acc;
}

// ---------------- aggregation with fused BN+lrelu of previous layer -------
__global__ void aggbn_kernel(const float* __restrict__ pre,
                             const float* __restrict__ bnw, const float* __restrict__ bnb,
                             float* __restrict__ hout, int N, int bnidx) {
    __shared__ float sc[64], sh[64];
    if (threadIdx.x < 64) {
        int c = threadIdx.x;
        float m   = g_stats[bnidx * 128 + c] / (float)N;
        float var = g_stats[bnidx * 128 + 64 + c] / (float)N - m * m;
        float inv = rsqrtf(var + 1e-5f);
        float a   = bnw[c] * inv;
        sc[c] = a;
        sh[c] = bnb[c] - m * a;
    }
    __syncthreads();
    int wid  = (blockIdx.x * blockDim.x + threadIdx.x) >> 5;
    int lane = threadIdx.x & 31;
    if (wid >= N) return;
    float a0 = sc[lane * 2], a1 = sc[lane * 2 + 1];
    float c0 = sh[lane * 2], c1 = sh[lane * 2 + 1];
#define BNR(v) { v.x = fmaf(v.x, a0, c0); v.x = fmaxf(v.x, 0.01f * v.x); \
                 v.y = fmaf(v.y, a1, c1); v.y = fmaxf(v.y, 0.01f * v.y); }
    float2 acc = *(const float2*)&pre[wid * 64 + lane * 2];
    BNR(acc);
    int beg = g_rowptr[wid], end = g_rowptr[wid + 1];
    int e = beg;
    for (; e + 4 <= end; e += 4) {
        int s0 = g_srt[e], s1 = g_srt[e + 1], s2 = g_srt[e + 2], s3 = g_srt[e + 3];
        float2 v0 = *(const float2*)&pre[s0 * 64 + lane * 2];
        float2 v1 = *(const float2*)&pre[s1 * 64 + lane * 2];
        float2 v2 = *(const float2*)&pre[s2 * 64 + lane * 2];
        float2 v3 = *(const float2*)&pre[s3 * 64 + lane * 2];
        BNR(v0); BNR(v1); BNR(v2); BNR(v3);
        acc.x += (v0.x + v1.x) + (v2.x + v3.x);
        acc.y += (v0.y + v1.y) + (v2.y + v3.y);
    }
    for (; e < end; e++) {
        float2 v = *(const float2*)&pre[g_srt[e] * 64 + lane * 2];
        BNR(v);
        acc.x += v.x; acc.y += v.y;
    }
#undef BNR
    *(float2*)&hout[wid * 64 + lane * 2] = acc;
}

// ---------------- GIN MLP: dedup packed weights, H aliases A in smem ------
template <int K, int M1>
__global__ void __launch_bounds__(256) mlp_kernel(
    const float* __restrict__ hin,
    const float* __restrict__ wda, const float* __restrict__ ba,
    const float* __restrict__ wdb, const float* __restrict__ bb,
    float* __restrict__ out, int N, int bnidx)
{
    constexpr int TM = M1 / 32;
    extern __shared__ float smem[];
    float* A_s = smem;               // K*66, reused for H (M1*66, K==M1 here)
    float* RS  = smem + K * 66;      // 512
    float* RQ  = RS + 512;           // 512

    const int tid = threadIdx.x;
    const int n0  = blockIdx.x * 64;

    for (int i = tid; i < 64 * K; i += 256) {
        int nl = i / K, k = i - nl * K;
        int n = n0 + nl;
        A_s[k * 66 + nl] = (n < N) ? hin[n * K + k] : 0.f;
    }
    __syncthreads();

    const int lane = tid & 31, wrp = tid >> 5;
    const int nb = wrp * 8;

    // ---- GEMM1 ----
    ULL acc[TM][4];
#pragma unroll
    for (int i = 0; i < TM; i++)
#pragma unroll
        for (int p = 0; p < 4; p++) acc[i][p] = 0ULL;

#pragma unroll 8
    for (int k = 0; k < K; k++) {
        const float* row = &A_s[k * 66 + nb];
        ULL a0 = *(const ULL*)(row + 0);
        ULL a1 = *(const ULL*)(row + 2);
        ULL a2 = *(const ULL*)(row + 4);
        ULL a3 = *(const ULL*)(row + 6);
        if constexpr (TM == 4) {
            ulonglong2 q0 = *(const ulonglong2*)&wda[k * 256 + lane * 8];
            ulonglong2 q1 = *(const ulonglong2*)&wda[k * 256 + lane * 8 + 4];
            fma2(acc[0][0], q0.x, a0); fma2(acc[0][1], q0.x, a1); fma2(acc[0][2], q0.x, a2); fma2(acc[0][3], q0.x, a3);
            fma2(acc[1][0], q0.y, a0); fma2(acc[1][1], q0.y, a1); fma2(acc[1][2], q0.y, a2); fma2(acc[1][3], q0.y, a3);
            fma2(acc[2][0], q1.x, a0); fma2(acc[2][1], q1.x, a1); fma2(acc[2][2], q1.x, a2); fma2(acc[2][3], q1.x, a3);
            fma2(acc[3][0], q1.y, a0); fma2(acc[3][1], q1.y, a1); fma2(acc[3][2], q1.y, a2); fma2(acc[3][3], q1.y, a3);
        } else {
            ulonglong2 q = *(const ulonglong2*)&wda[k * 128 + lane * 4];
            fma2(acc[0][0], q.x, a0); fma2(acc[0][1], q.x, a1); fma2(acc[0][2], q.x, a2); fma2(acc[0][3], q.x, a3);
            fma2(acc[1][0], q.y, a0); fma2(acc[1][1], q.y, a1); fma2(acc[1][2], q.y, a2); fma2(acc[1][3], q.y, a3);
        }
    }

    // all reads of A_s complete before overwriting with H
    __syncthreads();
#pragma unroll
    for (int i = 0; i < TM; i++) {
        int m = lane * TM + i;
        float bv = ba[m];
#pragma unroll
        for (int p = 0; p < 4; p++) {
            float x, y; upk(acc[i][p], x, y);
            x += bv; y += bv;
            x = fmaxf(x, 0.01f * x); y = fmaxf(y, 0.01f * y);
            *(ULL*)&A_s[m * 66 + nb + 2 * p] = pk2(x, y);
        }
    }
    __syncthreads();

    // ---- GEMM2 ----
    ULL c2[2][4];
#pragma unroll
    for (int i = 0; i < 2; i++)
#pragma unroll
        for (int p = 0; p < 4; p++) c2[i][p] = 0ULL;
#pragma unroll 8
    for (int k = 0; k < M1; k++) {
        const float* row = &A_s[k * 66 + nb];
        ULL a0 = *(const ULL*)(row + 0);
        ULL a1 = *(const ULL*)(row + 2);
        ULL a2 = *(const ULL*)(row + 4);
        ULL a3 = *(const ULL*)(row + 6);
        ulonglong2 q = *(const ulonglong2*)&wdb[k * 128 + lane * 4];
        fma2(c2[0][0], q.x, a0); fma2(c2[0][1], q.x, a1); fma2(c2[0][2], q.x, a2); fma2(c2[0][3], q.x, a3);
        fma2(c2[1][0], q.y, a0); fma2(c2[1][1], q.y, a1); fma2(c2[1][2], q.y, a2); fma2(c2[1][3], q.y, a3);
    }
    float b0 = bb[lane * 2], b1 = bb[lane * 2 + 1];
    float s0 = 0.f, q0 = 0.f, s1 = 0.f, q1 = 0.f;
#pragma unroll
    for (int p = 0; p < 4; p++) {
        float x0, x1, y0, y1;
        upk(c2[0][p], x0, x1);
        upk(c2[1][p], y0, y1);
        int na = n0 + nb + 2 * p;
        if (na < N) {
            float o0 = x0 + b0, o1 = y0 + b1;
            *(float2*)&out[na * 64 + lane * 2] = make_float2(o0, o1);
            s0 += o0; q0 = fmaf(o0, o0, q0); s1 += o1; q1 = fmaf(o1, o1, q1);
        }
        if (na + 1 < N) {
            float o0 = x1 + b0, o1 = y1 + b1;
            *(float2*)&out[(na + 1) * 64 + lane * 2] = make_float2(o0, o1);
            s0 += o0; q0 = fmaf(o0, o0, q0); s1 += o1; q1 = fmaf(o1, o1, q1);
        }
    }
    RS[wrp * 64 + lane * 2] = s0; RS[wrp * 64 + lane * 2 + 1] = s1;
    RQ[wrp * 64 + lane * 2] = q0; RQ[wrp * 64 + lane * 2 + 1] = q1;
    __syncthreads();
    if (tid < 128) {
        int c = tid & 63;
        const float* P = (tid >= 64) ? RQ : RS;
        float v = 0.f;
#pragma unroll
        for (int w = 0; w < 8; w++) v += P[w * 64 + c];
        atomicAdd(&g_stats[bnidx * 128 + ((tid >= 64) ? 64 : 0) + c], v);
    }
}

// ---------------- fc1 head GEMM (K=320), fused BN-in + stats-out ----------
__global__ void __launch_bounds__(256) fc1_kernel(
    const float* __restrict__ ed, const float* __restrict__ el,
    const int* __restrict__ ndeg, const int* __restrict__ nlab,
    const float* __restrict__ pre1, const float* __restrict__ pre2, const float* __restrict__ pre3,
    const float* __restrict__ bn0w, const float* __restrict__ bn0b,
    const float* __restrict__ bn1w, const float* __restrict__ bn1b,
    const float* __restrict__ bn2w, const float* __restrict__ bn2b,
    const float* __restrict__ fb,
    float* __restrict__ out, int N)
{
    extern __shared__ float smem[];
    float* A_s = smem;                 // 320*66 = 21120
    float* RS  = A_s + 21120;          // 512
    float* RQ  = RS + 512;             // 512
    float* sc  = RQ + 512;             // 192
    float* sh  = sc + 192;             // 192

    const int tid = threadIdx.x;
    if (tid < 192) {
        int l = tid >> 6, c = tid & 63;
        const float* w = (l == 0) ? bn0w : ((l == 1) ? bn1w : bn2w);
        const float* b = (l == 0) ? bn0b : ((l == 1) ? bn1b : bn2b);
        float m   = g_stats[l * 128 + c] / (float)N;
        float var = g_stats[l * 128 + 64 + c] / (float)N - m * m;
        float inv = rsqrtf(var + 1e-5f);
        float a   = w[c] * inv;
        sc[tid] = a;
        sh[tid] = b[c] - m * a;
    }
    __syncthreads();

    const int n0 = blockIdx.x * 64;
    for (int i = tid; i < 64 * 320; i += 256) {
        int nl = i / 320, k = i - nl * 320;
        int n = n0 + nl;
        float v = 0.f;
        if (n < N) {
            if (k < 64)       v = ed[ndeg[n] * 64 + k];
            else if (k < 128) v = el[nlab[n] * 64 + (k - 64)];
            else {
                int l = (k - 128) >> 6, c = (k - 128) & 63;
                const float* pr = (l == 0) ? pre1 : ((l == 1) ? pre2 : pre3);
                float p = fmaf(pr[n * 64 + c], sc[l * 64 + c], sh[l * 64 + c]);
                v = fmaxf(p, 0.01f * p);
            }
        }
        A_s[k * 66 + nl] = v;
    }
    __syncthreads();

    const int lane = tid & 31, wrp = tid >> 5;
    const int nb = wrp * 8;

    ULL c2[2][4];
#pragma unroll
    for (int i = 0; i < 2; i++)
#pragma unroll
        for (int p = 0; p < 4; p++) c2[i][p] = 0ULL;

#pragma unroll 8
    for (int k = 0; k < 320; k++) {
        const float* row = &A_s[k * 66 + nb];
        ULL a0 = *(const ULL*)(row + 0);
        ULL a1 = *(const ULL*)(row + 2);
        ULL a2 = *(const ULL*)(row + 4);
        ULL a3 = *(const ULL*)(row + 6);
        ulonglong2 q = *(const ulonglong2*)&g_fc1d[k * 128 + lane * 4];
        fma2(c2[0][0], q.x, a0); fma2(c2[0][1], q.x, a1); fma2(c2[0][2], q.x, a2); fma2(c2[0][3], q.x, a3);
        fma2(c2[1][0], q.y, a0); fma2(c2[1][1], q.y, a1); fma2(c2[1][2], q.y, a2); fma2(c2[1][3], q.y, a3);
    }

    float b0 = fb[lane * 2], b1 = fb[lane * 2 + 1];
    float s0 = 0.f, q0 = 0.f, s1 = 0.f, q1 = 0.f;
#pragma unroll
    for (int p = 0; p < 4; p++) {
        float x0, x1, y0, y1;
        upk(c2[0][p], x0, x1);
        upk(c2[1][p], y0, y1);
        int na = n0 + nb + 2 * p;
        if (na < N) {
            float o0 = x0 + b0, o1 = y0 + b1;
            *(float2*)&out[na * 64 + lane * 2] = make_float2(o0, o1);
            s0 += o0; q0 = fmaf(o0, o0, q0); s1 += o1; q1 = fmaf(o1, o1, q1);
        }
        if (na + 1 < N) {
            float o0 = x1 + b0, o1 = y1 + b1;
            *(float2*)&out[(na + 1) * 64 + lane * 2] = make_float2(o0, o1);
            s0 += o0; q0 = fmaf(o0, o0, q0); s1 += o1; q1 = fmaf(o1, o1, q1);
        }
    }
    RS[wrp * 64 + lane * 2] = s0; RS[wrp * 64 + lane * 2 + 1] = s1;
    RQ[wrp * 64 + lane * 2] = q0; RQ[wrp * 64 + lane * 2 + 1] = q1;
    __syncthreads();
    if (tid < 128) {
        int c = tid & 63;
        const float* P = (tid >= 64) ? RQ : RS;
        float v = 0.f;
#pragma unroll
        for (int w = 0; w < 8; w++) v += P[w * 64 + c];
        atomicAdd(&g_stats[3 * 128 + ((tid >= 64) ? 64 : 0) + c], v);
    }
}

// ---------------- final head ----------------
__global__ void final_kernel(const float* __restrict__ hpre,
                             const float* __restrict__ bnw, const float* __restrict__ bnb,
                             const float* __restrict__ fc2w, const float* __restrict__ fc2b,
                             float* __restrict__ out, int N) {
    __shared__ float sc[64], sh[64], w2s[64];
    if (threadIdx.x < 64) {
        int c = threadIdx.x;
        float m   = g_stats[3 * 128 + c] / (float)N;
        float var = g_stats[3 * 128 + 64 + c] / (float)N - m * m;
        float inv = rsqrtf(var + 1e-5f);
        float a   = bnw[c] * inv;
        sc[c]  = a;
        sh[c]  = bnb[c] - m * a;
        w2s[c] = fc2w[c];
    }
    __syncthreads();
    int wid  = (blockIdx.x * blockDim.x + threadIdx.x) >> 5;
    int lane = threadIdx.x & 31;
    if (wid >= N) return;
    float2 v = *(const float2*)&hpre[wid * 64 + lane * 2];
    float x = fmaf(v.x, sc[lane * 2], sh[lane * 2]);         x = fmaxf(x, 0.01f * x);
    float y = fmaf(v.y, sc[lane * 2 + 1], sh[lane * 2 + 1]); y = fmaxf(y, 0.01f * y);
    float acc = fmaf(x, w2s[lane * 2], y * w2s[lane * 2 + 1]);
#pragma unroll
    for (int off = 16; off; off >>= 1) acc += __shfl_xor_sync(0xffffffffu, acc, off);
    if (lane == 0) out[wid] = 1.f / (1.f + expf(-(acc + fc2b[0])));
}

// ---------------- launch ----------------
extern "C" void kernel_launch(void* const* d_in, const int* in_sizes, int n_in,
                              void* d_out, int out_size) {
    const float* emb_deg = (const float*)d_in[0];
    const float* emb_lab = (const float*)d_in[1];
    const float* w0a = (const float*)d_in[2];  const float* b0a = (const float*)d_in[3];
    const float* w0b = (const float*)d_in[4];  const float* b0b = (const float*)d_in[5];
    const float* bn0w = (const float*)d_in[6]; const float* bn0b = (const float*)d_in[7];
    const float* w1a = (const float*)d_in[8];  const float* b1a = (const float*)d_in[9];
    const float* w1b = (const float*)d_in[10]; const float* b1b = (const float*)d_in[11];
    const float* bn1w = (const float*)d_in[12]; const float* bn1b = (const float*)d_in[13];
    const float* w2a = (const float*)d_in[14]; const float* b2a = (const float*)d_in[15];
    const float* w2b = (const float*)d_in[16]; const float* b2b = (const float*)d_in[17];
    const float* bn2w = (const float*)d_in[18]; const float* bn2b = (const float*)d_in[19];
    const float* fc1w = (const float*)d_in[20]; const float* fc1b = (const float*)d_in[21];
    const float* fcbnw = (const float*)d_in[22]; const float* fcbnb = (const float*)d_in[23];
    const float* fc2w = (const float*)d_in[24]; const float* fc2b = (const float*)d_in[25];
    const int* node_deg = (const int*)d_in[26];
    const int* node_lab = (const int*)d_in[27];
    const int* edge = (const int*)d_in[28];

    const int N = in_sizes[26];
    const int E = in_sizes[28] / 2;
    const int* src  = edge;
    const int* dstp = edge + E;
    float* out = (float*)d_out;

    float *hin, *pre1, *pre2, *pre3, *pre4;
    float *wd0a, *wd0b, *wd1a, *wd1b, *wd2a, *wd2b;
    cudaGetSymbolAddress((void**)&hin,  g_hin);
    cudaGetSymbolAddress((void**)&pre1, g_pre1);
    cudaGetSymbolAddress((void**)&pre2, g_pre2);
    cudaGetSymbolAddress((void**)&pre3, g_pre3);
    cudaGetSymbolAddress((void**)&pre4, g_pre4);
    cudaGetSymbolAddress((void**)&wd0a, g_wd0a);
    cudaGetSymbolAddress((void**)&wd0b, g_wd0b);
    cudaGetSymbolAddress((void**)&wd1a, g_wd1a);
    cudaGetSymbolAddress((void**)&wd1b, g_wd1b);
    cudaGetSymbolAddress((void**)&wd2a, g_wd2a);
    cudaGetSymbolAddress((void**)&wd2b, g_wd2b);

    const int TB = 256;
    const int mlpBlocks  = (N + 63) / 64;
    const int warpBlocks = (N * 32 + TB - 1) / TB;
    const int scanBlocks = (N + 255) / 256;
    const int prepBlocks = (61440 + 255) / 256;

    const int SM_MLP0 = (128 * 66 + 1024) * 4;   // 37888 (H aliases A)
    const int SM_MLP1 = (64 * 66 + 1024) * 4;    // 20992
    const int SM_FC1  = (21120 + 1024 + 384) * 4; // 90112
    cudaFuncSetAttribute(mlp_kernel<128, 128>, cudaFuncAttributeMaxDynamicSharedMemorySize, SM_MLP0);
    cudaFuncSetAttribute(mlp_kernel<64, 64>,   cudaFuncAttributeMaxDynamicSharedMemorySize, SM_MLP1);
    cudaFuncSetAttribute(fc1_kernel,           cudaFuncAttributeMaxDynamicSharedMemorySize, SM_FC1);

    // 1: histogram (g_cnt zero: static-init first call, re-zeroed by scatter)
    hist_kernel<<<(E + TB - 1) / TB, TB>>>(dstp, E);
    // 2: partial scan + weight dup-transpose
    scan_part_prep<<<scanBlocks + prepBlocks, 256>>>(N, scanBlocks, w0a, w0b, w1a, w1b, w2a, w2b, fc1w);
    // 3-4: scan
    scan_top<<<1, 256>>>(scanBlocks);
    scan_apply<<<scanBlocks, 256>>>(N);
    // 5: scatter + re-zero cnt/stats
    scatter_kernel<<<(E + TB - 1) / TB, TB>>>(src, dstp, E, N);

    // 6-7: layer 0
    agg0_kernel<<<warpBlocks, TB>>>(emb_deg, emb_lab, node_deg, node_lab, hin, N);
    mlp_kernel<128, 128><<<mlpBlocks, 256, SM_MLP0>>>(hin, wd0a, b0a, wd0b, b0b, pre1, N, 0);

    // 8-9: layer 1
    aggbn_kernel<<<warpBlocks, TB>>>(pre1, bn0w, bn0b, hin, N, 0);
    mlp_kernel<64, 64><<<mlpBlocks, 256, SM_MLP1>>>(hin, wd1a, b1a, wd1b, b1b, pre2, N, 1);

    // 10-11: layer 2
    aggbn_kernel<<<warpBlocks, TB>>>(pre2, bn1w, bn1b, hin, N, 1);
    mlp_kernel<64, 64><<<mlpBlocks, 256, SM_MLP1>>>(hin, wd2a, b2a, wd2b, b2b, pre3, N, 2);

    // 12-13: head
    fc1_kernel<<<mlpBlocks, 256, SM_FC1>>>(emb_deg, emb_lab, node_deg, node_lab,
                                           pre1, pre2, pre3,
                                           bn0w, bn0b, bn1w, bn1b, bn2w, bn2b,
                                           fc1b, pre4, N);
    final_kernel<<<warpBlocks, TB>>>(pre4, fcbnw, fcbnb, fc2w, fc2b, out, N);
}

// round 9
// speedup vs baseline: 1.3051x; 1.2321x over previous
#include <cuda_runtime.h>
#include <math.h>

#define NN 50000
#define NE 800000
typedef unsigned long long ULL;

// ---------------- device scratch ----------------
__device__ float g_hin [NN * 128];
__device__ float g_pre1[NN * 64];
__device__ float g_pre2[NN * 64];
__device__ float g_pre3[NN * 64];
__device__ float g_pre4[NN * 64];
// compact transposed weights: wt[k*M + m] = w[m*K + k]
__device__ float g_wt0a[128 * 128];
__device__ float g_wt0b[128 * 64];
__device__ float g_wt1a[64 * 64];
__device__ float g_wt1b[64 * 64];
__device__ float g_wt2a[64 * 64];
__device__ float g_wt2b[64 * 64];
__device__ float g_fc1t[320 * 64];
__device__ int   g_cnt[NN];
__device__ int   g_rowptr[NN + 1];
__device__ int   g_cursor[NN];
__device__ int   g_srt[NE];
__device__ int   g_bsum[256];
__device__ int   g_boff[256];
__device__ float g_stats[4 * 128];   // per BN: [0:64) sum, [64:128) sumsq

#define ASTRIDE 68   // floats per smem row: 16B-aligned, enables LDS.128

// ---------------- f32x2 helpers ----------------
__device__ __forceinline__ ULL pk2(float x, float y) {
    ULL r; asm("mov.b64 %0, {%1,%2};" : "=l"(r) : "f"(x), "f"(y)); return r;
}
__device__ __forceinline__ void upk(ULL v, float& x, float& y) {
    asm("mov.b64 {%0,%1}, %2;" : "=f"(x), "=f"(y) : "l"(v));
}
__device__ __forceinline__ void fma2(ULL& d, ULL a, ULL b) {
    asm("fma.rn.f32x2 %0, %1, %2, %0;" : "+l"(d) : "l"(a), "l"(b));
}

// ---------------- launch 1: histogram by dst ----------------
__global__ void hist_kernel(const int* __restrict__ dst, int E) {
    int i = blockIdx.x * blockDim.x + threadIdx.x;
    if (i < E) atomicAdd(&g_cnt[dst[i]], 1);
}

// ---------------- launch 2: partial scan + weight transpose ----------
__global__ void scan_part_prep(int N, int scanBlocks,
                               const float* __restrict__ w0a, const float* __restrict__ w0b,
                               const float* __restrict__ w1a, const float* __restrict__ w1b,
                               const float* __restrict__ w2a, const float* __restrict__ w2b,
                               const float* __restrict__ fc1w) {
    int t = threadIdx.x;
    if ((int)blockIdx.x < scanBlocks) {
        __shared__ int sm[256];
        int idx = blockIdx.x * 256 + t;
        sm[t] = (idx < N) ? g_cnt[idx] : 0;
        __syncthreads();
        for (int o = 128; o; o >>= 1) { if (t < o) sm[t] += sm[t + o]; __syncthreads(); }
        if (t == 0) g_bsum[blockIdx.x] = sm[0];
        return;
    }
    int j = (blockIdx.x - scanBlocks) * 256 + t;
    if (j < 16384) { int m = j >> 7, k = j & 127; g_wt0a[k * 128 + m] = w0a[j]; return; }
    if ((j -= 16384) < 8192) { int m = j >> 7, k = j & 127; g_wt0b[k * 64 + m] = w0b[j]; return; }
    if ((j -= 8192) < 4096)  { int m = j >> 6, k = j & 63; g_wt1a[k * 64 + m] = w1a[j]; return; }
    if ((j -= 4096) < 4096)  { int m = j >> 6, k = j & 63; g_wt1b[k * 64 + m] = w1b[j]; return; }
    if ((j -= 4096) < 4096)  { int m = j >> 6, k = j & 63; g_wt2a[k * 64 + m] = w2a[j]; return; }
    if ((j -= 4096) < 4096)  { int m = j >> 6, k = j & 63; g_wt2b[k * 64 + m] = w2b[j]; return; }
    if ((j -= 4096) < 20480) { int m = j / 320, k = j - m * 320; g_fc1t[k * 64 + m] = fc1w[j]; return; }
}

// ---------------- launch 3/4: scan top + apply ----------------
__global__ void scan_top(int B) {
    __shared__ int sm[256];
    int t = threadIdx.x;
    sm[t] = (t < B) ? g_bsum[t] : 0;
    __syncthreads();
    for (int o = 1; o < 256; o <<= 1) {
        int u = (t >= o) ? sm[t - o] : 0;
        __syncthreads(); sm[t] += u; __syncthreads();
    }
    g_boff[t] = (t > 0) ? sm[t - 1] : 0;
}
__global__ void scan_apply(int N) {
    __shared__ int sm[256];
    int t = threadIdx.x, idx = blockIdx.x * 256 + t;
    int v = (idx < N) ? g_cnt[idx] : 0;
    sm[t] = v;
    __syncthreads();
    for (int o = 1; o < 256; o <<= 1) {
        int u = (t >= o) ? sm[t - o] : 0;
        __syncthreads(); sm[t] += u; __syncthreads();
    }
    int excl = sm[t] - v + g_boff[blockIdx.x];
    if (idx < N) {
        g_rowptr[idx] = excl;
        g_cursor[idx] = excl;
        if (idx == N - 1) g_rowptr[N] = excl + v;
    }
}

// ---------------- launch 5: scatter + re-zero cnt/stats ----------------
__global__ void scatter_kernel(const int* __restrict__ src, const int* __restrict__ dst, int E, int N) {
    int i = blockIdx.x * blockDim.x + threadIdx.x;
    if (i < E) {
        int p = atomicAdd(&g_cursor[dst[i]], 1);
        g_srt[p] = src[i];
    }
    if (i < N) g_cnt[i] = 0;
    if (i < 512) g_stats[i] = 0.f;
}

// ---------------- launch 6: layer-0 aggregation from L1-resident tables ---
__global__ void agg0_kernel(const float* __restrict__ ed, const float* __restrict__ el,
                            const int* __restrict__ ndeg, const int* __restrict__ nlab,
                            float* __restrict__ hout, int N) {
    int wid  = (blockIdx.x * blockDim.x + threadIdx.x) >> 5;
    int lane = threadIdx.x & 31;
    if (wid >= N) return;
    const float* tbl    = (lane < 16) ? ed : el;
    const int*   idxarr = (lane < 16) ? ndeg : nlab;
    const int    offi   = (lane & 15) * 4;

    float4 acc = *(const float4*)&tbl[idxarr[wid] * 64 + offi];
    int beg = g_rowptr[wid], end = g_rowptr[wid + 1];
    int e = beg;
    for (; e + 4 <= end; e += 4) {
        int s0 = g_srt[e], s1 = g_srt[e + 1], s2 = g_srt[e + 2], s3 = g_srt[e + 3];
        int i0 = idxarr[s0], i1 = idxarr[s1], i2 = idxarr[s2], i3 = idxarr[s3];
        float4 v0 = *(const float4*)&tbl[i0 * 64 + offi];
        float4 v1 = *(const float4*)&tbl[i1 * 64 + offi];
        float4 v2 = *(const float4*)&tbl[i2 * 64 + offi];
        float4 v3 = *(const float4*)&tbl[i3 * 64 + offi];
        acc.x += (v0.x + v1.x) + (v2.x + v3.x);
        acc.y += (v0.y + v1.y) + (v2.y + v3.y);
        acc.z += (v0.z + v1.z) + (v2.z + v3.z);
        acc.w += (v0.w + v1.w) + (v2.w + v3.w);
    }
    for (; e < end; e++) {
        float4 v = *(const float4*)&tbl[idxarr[g_srt[e]] * 64 + offi];
        acc.x += v.x; acc.y += v.y; acc.z += v.z; acc.w += v.w;
    }
    *(float4*)&hout[wid * 128 + lane * 4] = acc;
}

// ---------------- aggregation with fused BN+lrelu of previous layer -------
__global__ void aggbn_kernel(const float* __restrict__ pre,
                             const float* __restrict__ bnw, const float* __restrict__ bnb,
                             float* __restrict__ hout, int N, int bnidx) {
    __shared__ float sc[64], sh[64];
    if (threadIdx.x < 64) {
        int c = threadIdx.x;
        float m   = g_stats[bnidx * 128 + c] / (float)N;
        float var = g_stats[bnidx * 128 + 64 + c] / (float)N - m * m;
        float inv = rsqrtf(var + 1e-5f);
        float a   = bnw[c] * inv;
        sc[c] = a;
        sh[c] = bnb[c] - m * a;
    }
    __syncthreads();
    int wid  = (blockIdx.x * blockDim.x + threadIdx.x) >> 5;
    int lane = threadIdx.x & 31;
    if (wid >= N) return;
    float a0 = sc[lane * 2], a1 = sc[lane * 2 + 1];
    float c0 = sh[lane * 2], c1 = sh[lane * 2 + 1];
#define BNR(v) { v.x = fmaf(v.x, a0, c0); v.x = fmaxf(v.x, 0.01f * v.x); \
                 v.y = fmaf(v.y, a1, c1); v.y = fmaxf(v.y, 0.01f * v.y); }
    float2 acc = *(const float2*)&pre[wid * 64 + lane * 2];
    BNR(acc);
    int beg = g_rowptr[wid], end = g_rowptr[wid + 1];
    int e = beg;
    for (; e + 4 <= end; e += 4) {
        int s0 = g_srt[e], s1 = g_srt[e + 1], s2 = g_srt[e + 2], s3 = g_srt[e + 3];
        float2 v0 = *(const float2*)&pre[s0 * 64 + lane * 2];
        float2 v1 = *(const float2*)&pre[s1 * 64 + lane * 2];
        float2 v2 = *(const float2*)&pre[s2 * 64 + lane * 2];
        float2 v3 = *(const float2*)&pre[s3 * 64 + lane * 2];
        BNR(v0); BNR(v1); BNR(v2); BNR(v3);
        acc.x += (v0.x + v1.x) + (v2.x + v3.x);
        acc.y += (v0.y + v1.y) + (v2.y + v3.y);
    }
    for (; e < end; e++) {
        float2 v = *(const float2*)&pre[g_srt[e] * 64 + lane * 2];
        BNR(v);
        acc.x += v.x; acc.y += v.y;
    }
#undef BNR
    *(float2*)&hout[wid * 64 + lane * 2] = acc;
}

// ---------------- GIN MLP: compact weights + pk2, LDS.128 nodes, aliased --
template <int K, int M1>
__global__ void __launch_bounds__(256) mlp_kernel(
    const float* __restrict__ hin,
    const float* __restrict__ wta, const float* __restrict__ ba,
    const float* __restrict__ wtb, const float* __restrict__ bb,
    float* __restrict__ out, int N, int bnidx)
{
    constexpr int TM = M1 / 32;
    extern __shared__ float smem[];
    float* A_s = smem;                   // K*ASTRIDE (reused for H, M1<=K)
    float* RS  = smem + K * ASTRIDE;     // 512
    float* RQ  = RS + 512;               // 512

    const int tid = threadIdx.x;
    const int n0  = blockIdx.x * 64;

    for (int i = tid; i < 64 * K; i += 256) {
        int nl = i / K, k = i - nl * K;
        int n = n0 + nl;
        A_s[k * ASTRIDE + nl] = (n < N) ? hin[n * K + k] : 0.f;
    }
    __syncthreads();

    const int lane = tid & 31, wrp = tid >> 5;
    const int nb = wrp * 8;

    // ---- GEMM1 ----
    ULL acc[TM][4];
#pragma unroll
    for (int i = 0; i < TM; i++)
#pragma unroll
        for (int p = 0; p < 4; p++) acc[i][p] = 0ULL;

#pragma unroll 8
    for (int k = 0; k < K; k++) {
        const float* row = &A_s[k * ASTRIDE + nb];
        ulonglong2 n01 = *(const ulonglong2*)(row);      // nodes nb..nb+3
        ulonglong2 n23 = *(const ulonglong2*)(row + 4);  // nodes nb+4..nb+7
        ULL a0 = n01.x, a1 = n01.y, a2 = n23.x, a3 = n23.y;
        if constexpr (TM == 4) {
            float4 w4 = *(const float4*)&wta[k * M1 + lane * 4];
            ULL w0 = pk2(w4.x, w4.x), w1 = pk2(w4.y, w4.y);
            ULL w2 = pk2(w4.z, w4.z), w3 = pk2(w4.w, w4.w);
            fma2(acc[0][0], w0, a0); fma2(acc[0][1], w0, a1); fma2(acc[0][2], w0, a2); fma2(acc[0][3], w0, a3);
            fma2(acc[1][0], w1, a0); fma2(acc[1][1], w1, a1); fma2(acc[1][2], w1, a2); fma2(acc[1][3], w1, a3);
            fma2(acc[2][0], w2, a0); fma2(acc[2][1], w2, a1); fma2(acc[2][2], w2, a2); fma2(acc[2][3], w2, a3);
            fma2(acc[3][0], w3, a0); fma2(acc[3][1], w3, a1); fma2(acc[3][2], w3, a2); fma2(acc[3][3], w3, a3);
        } else {
            float2 wv = *(const float2*)&wta[k * M1 + lane * 2];
            ULL w0 = pk2(wv.x, wv.x), w1 = pk2(wv.y, wv.y);
            fma2(acc[0][0], w0, a0); fma2(acc[0][1], w0, a1); fma2(acc[0][2], w0, a2); fma2(acc[0][3], w0, a3);
            fma2(acc[1][0], w1, a0); fma2(acc[1][1], w1, a1); fma2(acc[1][2], w1, a2); fma2(acc[1][3], w1, a3);
        }
    }

    __syncthreads();   // all A reads done before overwrite with H
#pragma unroll
    for (int i = 0; i < TM; i++) {
        int m = lane * TM + i;
        float bv = ba[m];
#pragma unroll
        for (int p = 0; p < 4; p++) {
            float x, y; upk(acc[i][p], x, y);
            x += bv; y += bv;
            x = fmaxf(x, 0.01f * x); y = fmaxf(y, 0.01f * y);
            *(ULL*)&A_s[m * ASTRIDE + nb + 2 * p] = pk2(x, y);
        }
    }
    __syncthreads();

    // ---- GEMM2 ----
    ULL c2[2][4];
#pragma unroll
    for (int i = 0; i < 2; i++)
#pragma unroll
        for (int p = 0; p < 4; p++) c2[i][p] = 0ULL;
#pragma unroll 8
    for (int k = 0; k < M1; k++) {
        const float* row = &A_s[k * ASTRIDE + nb];
        ulonglong2 n01 = *(const ulonglong2*)(row);
        ulonglong2 n23 = *(const ulonglong2*)(row + 4);
        ULL a0 = n01.x, a1 = n01.y, a2 = n23.x, a3 = n23.y;
        float2 wv = *(const float2*)&wtb[k * 64 + lane * 2];
        ULL w0 = pk2(wv.x, wv.x), w1 = pk2(wv.y, wv.y);
        fma2(c2[0][0], w0, a0); fma2(c2[0][1], w0, a1); fma2(c2[0][2], w0, a2); fma2(c2[0][3], w0, a3);
        fma2(c2[1][0], w1, a0); fma2(c2[1][1], w1, a1); fma2(c2[1][2], w1, a2); fma2(c2[1][3], w1, a3);
    }
    float b0 = bb[lane * 2], b1 = bb[lane * 2 + 1];
    float s0 = 0.f, q0 = 0.f, s1 = 0.f, q1 = 0.f;
#pragma unroll
    for (int p = 0; p < 4; p++) {
        float x0, x1, y0, y1;
        upk(c2[0][p], x0, x1);
        upk(c2[1][p], y0, y1);
        int na = n0 + nb + 2 * p;
        if (na < N) {
            float o0 = x0 + b0, o1 = y0 + b1;
            *(float2*)&out[na * 64 + lane * 2] = make_float2(o0, o1);
            s0 += o0; q0 = fmaf(o0, o0, q0); s1 += o1; q1 = fmaf(o1, o1, q1);
        }
        if (na + 1 < N) {
            float o0 = x1 + b0, o1 = y1 + b1;
            *(float2*)&out[(na + 1) * 64 + lane * 2] = make_float2(o0, o1);
            s0 += o0; q0 = fmaf(o0, o0, q0); s1 += o1; q1 = fmaf(o1, o1, q1);
        }
    }
    RS[wrp * 64 + lane * 2] = s0; RS[wrp * 64 + lane * 2 + 1] = s1;
    RQ[wrp * 64 + lane * 2] = q0; RQ[wrp * 64 + lane * 2 + 1] = q1;
    __syncthreads();
    if (tid < 128) {
        int c = tid & 63;
        const float* P = (tid >= 64) ? RQ : RS;
        float v = 0.f;
#pragma unroll
        for (int w = 0; w < 8; w++) v += P[w * 64 + c];
        atomicAdd(&g_stats[bnidx * 128 + ((tid >= 64) ? 64 : 0) + c], v);
    }
}

// ---------------- fc1 head GEMM (K=320), fused BN-in + stats-out ----------
__global__ void __launch_bounds__(256) fc1_kernel(
    const float* __restrict__ ed, const float* __restrict__ el,
    const int* __restrict__ ndeg, const int* __restrict__ nlab,
    const float* __restrict__ pre1, const float* __restrict__ pre2, const float* __restrict__ pre3,
    const float* __restrict__ bn0w, const float* __restrict__ bn0b,
    const float* __restrict__ bn1w, const float* __restrict__ bn1b,
    const float* __restrict__ bn2w, const float* __restrict__ bn2b,
    const float* __restrict__ fb,
    float* __restrict__ out, int N)
{
    extern __shared__ float smem[];
    float* A_s = smem;                      // 320*ASTRIDE
    float* RS  = A_s + 320 * ASTRIDE;       // 512
    float* RQ  = RS + 512;                  // 512
    float* sc  = RQ + 512;                  // 192
    float* sh  = sc + 192;                  // 192

    const int tid = threadIdx.x;
    if (tid < 192) {
        int l = tid >> 6, c = tid & 63;
        const float* w = (l == 0) ? bn0w : ((l == 1) ? bn1w : bn2w);
        const float* b = (l == 0) ? bn0b : ((l == 1) ? bn1b : bn2b);
        float m   = g_stats[l * 128 + c] / (float)N;
        float var = g_stats[l * 128 + 64 + c] / (float)N - m * m;
        float inv = rsqrtf(var + 1e-5f);
        float a   = w[c] * inv;
        sc[tid] = a;
        sh[tid] = b[c] - m * a;
    }
    __syncthreads();

    const int n0 = blockIdx.x * 64;
    for (int i = tid; i < 64 * 320; i += 256) {
        int nl = i / 320, k = i - nl * 320;
        int n = n0 + nl;
        float v = 0.f;
        if (n < N) {
            if (k < 64)       v = ed[ndeg[n] * 64 + k];
            else if (k < 128) v = el[nlab[n] * 64 + (k - 64)];
            else {
                int l = (k - 128) >> 6, c = (k - 128) & 63;
                const float* pr = (l == 0) ? pre1 : ((l == 1) ? pre2 : pre3);
                float p = fmaf(pr[n * 64 + c], sc[l * 64 + c], sh[l * 64 + c]);
                v = fmaxf(p, 0.01f * p);
            }
        }
        A_s[k * ASTRIDE + nl] = v;
    }
    __syncthreads();

    const int lane = tid & 31, wrp = tid >> 5;
    const int nb = wrp * 8;

    ULL c2[2][4];
#pragma unroll
    for (int i = 0; i < 2; i++)
#pragma unroll
        for (int p = 0; p < 4; p++) c2[i][p] = 0ULL;

#pragma unroll 8
    for (int k = 0; k < 320; k++) {
        const float* row = &A_s[k * ASTRIDE + nb];
        ulonglong2 n01 = *(const ulonglong2*)(row);
        ulonglong2 n23 = *(const ulonglong2*)(row + 4);
        ULL a0 = n01.x, a1 = n01.y, a2 = n23.x, a3 = n23.y;
        float2 wv = *(const float2*)&g_fc1t[k * 64 + lane * 2];
        ULL w0 = pk2(wv.x, wv.x), w1 = pk2(wv.y, wv.y);
        fma2(c2[0][0], w0, a0); fma2(c2[0][1], w0, a1); fma2(c2[0][2], w0, a2); fma2(c2[0][3], w0, a3);
        fma2(c2[1][0], w1, a0); fma2(c2[1][1], w1, a1); fma2(c2[1][2], w1, a2); fma2(c2[1][3], w1, a3);
    }

    float b0 = fb[lane * 2], b1 = fb[lane * 2 + 1];
    float s0 = 0.f, q0 = 0.f, s1 = 0.f, q1 = 0.f;
#pragma unroll
    for (int p = 0; p < 4; p++) {
        float x0, x1, y0, y1;
        upk(c2[0][p], x0, x1);
        upk(c2[1][p], y0, y1);
        int na = n0 + nb + 2 * p;
        if (na < N) {
            float o0 = x0 + b0, o1 = y0 + b1;
            *(float2*)&out[na * 64 + lane * 2] = make_float2(o0, o1);
            s0 += o0; q0 = fmaf(o0, o0, q0); s1 += o1; q1 = fmaf(o1, o1, q1);
        }
        if (na + 1 < N) {
            float o0 = x1 + b0, o1 = y1 + b1;
            *(float2*)&out[(na + 1) * 64 + lane * 2] = make_float2(o0, o1);
            s0 += o0; q0 = fmaf(o0, o0, q0); s1 += o1; q1 = fmaf(o1, o1, q1);
        }
    }
    RS[wrp * 64 + lane * 2] = s0; RS[wrp * 64 + lane * 2 + 1] = s1;
    RQ[wrp * 64 + lane * 2] = q0; RQ[wrp * 64 + lane * 2 + 1] = q1;
    __syncthreads();
    if (tid < 128) {
        int c = tid & 63;
        const float* P = (tid >= 64) ? RQ : RS;
        float v = 0.f;
#pragma unroll
        for (int w = 0; w < 8; w++) v += P[w * 64 + c];
        atomicAdd(&g_stats[3 * 128 + ((tid >= 64) ? 64 : 0) + c], v);
    }
}

// ---------------- final head ----------------
__global__ void final_kernel(const float* __restrict__ hpre,
                             const float* __restrict__ bnw, const float* __restrict__ bnb,
                             const float* __restrict__ fc2w, const float* __restrict__ fc2b,
                             float* __restrict__ out, int N) {
    __shared__ float sc[64], sh[64], w2s[64];
    if (threadIdx.x < 64) {
        int c = threadIdx.x;
        float m   = g_stats[3 * 128 + c] / (float)N;
        float var = g_stats[3 * 128 + 64 + c] / (float)N - m * m;
        float inv = rsqrtf(var + 1e-5f);
        float a   = bnw[c] * inv;
        sc[c]  = a;
        sh[c]  = bnb[c] - m * a;
        w2s[c] = fc2w[c];
    }
    __syncthreads();
    int wid  = (blockIdx.x * blockDim.x + threadIdx.x) >> 5;
    int lane = threadIdx.x & 31;
    if (wid >= N) return;
    float2 v = *(const float2*)&hpre[wid * 64 + lane * 2];
    float x = fmaf(v.x, sc[lane * 2], sh[lane * 2]);         x = fmaxf(x, 0.01f * x);
    float y = fmaf(v.y, sc[lane * 2 + 1], sh[lane * 2 + 1]); y = fmaxf(y, 0.01f * y);
    float acc = fmaf(x, w2s[lane * 2], y * w2s[lane * 2 + 1]);
#pragma unroll
    for (int off = 16; off; off >>= 1) acc += __shfl_xor_sync(0xffffffffu, acc, off);
    if (lane == 0) out[wid] = 1.f / (1.f + expf(-(acc + fc2b[0])));
}

// ---------------- launch ----------------
extern "C" void kernel_launch(void* const* d_in, const int* in_sizes, int n_in,
                              void* d_out, int out_size) {
    const float* emb_deg = (const float*)d_in[0];
    const float* emb_lab = (const float*)d_in[1];
    const float* w0a = (const float*)d_in[2];  const float* b0a = (const float*)d_in[3];
    const float* w0b = (const float*)d_in[4];  const float* b0b = (const float*)d_in[5];
    const float* bn0w = (const float*)d_in[6]; const float* bn0b = (const float*)d_in[7];
    const float* w1a = (const float*)d_in[8];  const float* b1a = (const float*)d_in[9];
    const float* w1b = (const float*)d_in[10]; const float* b1b = (const float*)d_in[11];
    const float* bn1w = (const float*)d_in[12]; const float* bn1b = (const float*)d_in[13];
    const float* w2a = (const float*)d_in[14]; const float* b2a = (const float*)d_in[15];
    const float* w2b = (const float*)d_in[16]; const float* b2b = (const float*)d_in[17];
    const float* bn2w = (const float*)d_in[18]; const float* bn2b = (const float*)d_in[19];
    const float* fc1w = (const float*)d_in[20]; const float* fc1b = (const float*)d_in[21];
    const float* fcbnw = (const float*)d_in[22]; const float* fcbnb = (const float*)d_in[23];
    const float* fc2w = (const float*)d_in[24]; const float* fc2b = (const float*)d_in[25];
    const int* node_deg = (const int*)d_in[26];
    const int* node_lab = (const int*)d_in[27];
    const int* edge = (const int*)d_in[28];

    const int N = in_sizes[26];
    const int E = in_sizes[28] / 2;
    const int* src  = edge;
    const int* dstp = edge + E;
    float* out = (float*)d_out;

    float *hin, *pre1, *pre2, *pre3, *pre4;
    float *wt0a, *wt0b, *wt1a, *wt1b, *wt2a, *wt2b;
    cudaGetSymbolAddress((void**)&hin,  g_hin);
    cudaGetSymbolAddress((void**)&pre1, g_pre1);
    cudaGetSymbolAddress((void**)&pre2, g_pre2);
    cudaGetSymbolAddress((void**)&pre3, g_pre3);
    cudaGetSymbolAddress((void**)&pre4, g_pre4);
    cudaGetSymbolAddress((void**)&wt0a, g_wt0a);
    cudaGetSymbolAddress((void**)&wt0b, g_wt0b);
    cudaGetSymbolAddress((void**)&wt1a, g_wt1a);
    cudaGetSymbolAddress((void**)&wt1b, g_wt1b);
    cudaGetSymbolAddress((void**)&wt2a, g_wt2a);
    cudaGetSymbolAddress((void**)&wt2b, g_wt2b);

    const int TB = 256;
    const int mlpBlocks  = (N + 63) / 64;
    const int warpBlocks = (N * 32 + TB - 1) / TB;
    const int scanBlocks = (N + 255) / 256;
    const int prepBlocks = (61440 + 255) / 256;

    const int SM_MLP0 = (128 * ASTRIDE + 1024) * 4;            // 38912
    const int SM_MLP1 = (64 * ASTRIDE + 1024) * 4;             // 21504
    const int SM_FC1  = (320 * ASTRIDE + 1024 + 384) * 4;      // 92672
    cudaFuncSetAttribute(mlp_kernel<128, 128>, cudaFuncAttributeMaxDynamicSharedMemorySize, SM_MLP0);
    cudaFuncSetAttribute(mlp_kernel<64, 64>,   cudaFuncAttributeMaxDynamicSharedMemorySize, SM_MLP1);
    cudaFuncSetAttribute(fc1_kernel,           cudaFuncAttributeMaxDynamicSharedMemorySize, SM_FC1);

    // 1: histogram (g_cnt zero: static-init first call, re-zeroed by scatter)
    hist_kernel<<<(E + TB - 1) / TB, TB>>>(dstp, E);
    // 2: partial scan + weight transpose
    scan_part_prep<<<scanBlocks + prepBlocks, 256>>>(N, scanBlocks, w0a, w0b, w1a, w1b, w2a, w2b, fc1w);
    // 3-4: scan
    scan_top<<<1, 256>>>(scanBlocks);
    scan_apply<<<scanBlocks, 256>>>(N);
    // 5: scatter + re-zero cnt/stats
    scatter_kernel<<<(E + TB - 1) / TB, TB>>>(src, dstp, E, N);

    // 6-7: layer 0
    agg0_kernel<<<warpBlocks, TB>>>(emb_deg, emb_lab, node_deg, node_lab, hin, N);
    mlp_kernel<128, 128><<<mlpBlocks, 256, SM_MLP0>>>(hin, wt0a, b0a, wt0b, b0b, pre1, N, 0);

    // 8-9: layer 1
    aggbn_kernel<<<warpBlocks, TB>>>(pre1, bn0w, bn0b, hin, N, 0);
    mlp_kernel<64, 64><<<mlpBlocks, 256, SM_MLP1>>>(hin, wt1a, b1a, wt1b, b1b, pre2, N, 1);

    // 10-11: layer 2
    aggbn_kernel<<<warpBlocks, TB>>>(pre2, bn1w, bn1b, hin, N, 1);
    mlp_kernel<64, 64><<<mlpBlocks, 256, SM_MLP1>>>(hin, wt2a, b2a, wt2b, b2b, pre3, N, 2);

    // 12-13: head
    fc1_kernel<<<mlpBlocks, 256, SM_FC1>>>(emb_deg, emb_lab, node_deg, node_lab,
                                           pre1, pre2, pre3,
                                           bn0w, bn0b, bn1w, bn1b, bn2w, bn2b,
                                           fc1b, pre4, N);
    final_kernel<<<warpBlocks, TB>>>(pre4, fcbnw, fcbnb, fc2w, fc2b, out, N);
}

// round 10
// speedup vs baseline: 1.3857x; 1.0618x over previous
#include <cuda_runtime.h>
#include <math.h>

#define NN 50000
#define NE 800000
typedef unsigned long long ULL;

// ---------------- device scratch ----------------
__device__ float g_hin [NN * 128];
__device__ float g_pre1[NN * 64];
__device__ float g_pre2[NN * 64];
__device__ float g_pre3[NN * 64];
__device__ float g_pre4[NN * 64];
// compact transposed weights: wt[k*M + m] = w[m*K + k]
__device__ float g_wt0a[128 * 128];
__device__ float g_wt0b[128 * 64];
__device__ float g_wt1a[64 * 64];
__device__ float g_wt1b[64 * 64];
__device__ float g_wt2a[64 * 64];
__device__ float g_wt2b[64 * 64];
__device__ float g_fc1t[320 * 64];
__device__ float g_U[1024 * 64];     // U[c][m] = x0_c @ fc1_w[:, :128]^T
__device__ int   g_cnt[NN];
__device__ int   g_rowptr[NN + 1];
__device__ int   g_cursor[NN];
__device__ int   g_srt[NE];
__device__ unsigned int g_part[256]; // lookback scan state: [31:30]=flag, [29:0]=value
__device__ float g_stats[4 * 128];   // per BN: [0:64) sum, [64:128) sumsq

#define ASTRIDE 68   // floats per smem row: 16B-aligned -> LDS.128 in GEMM loops

// ---------------- f32x2 helpers ----------------
__device__ __forceinline__ ULL pk2(float x, float y) {
    ULL r; asm("mov.b64 %0, {%1,%2};" : "=l"(r) : "f"(x), "f"(y)); return r;
}
__device__ __forceinline__ void upk(ULL v, float& x, float& y) {
    asm("mov.b64 {%0,%1}, %2;" : "=f"(x), "=f"(y) : "l"(v));
}
__device__ __forceinline__ void fma2(ULL& d, ULL a, ULL b) {
    asm("fma.rn.f32x2 %0, %1, %2, %0;" : "+l"(d) : "l"(a), "l"(b));
}

// ---------------- launch 1: histogram by dst ----------------
__global__ void hist_kernel(const int* __restrict__ dst, int E) {
    int i = blockIdx.x * blockDim.x + threadIdx.x;
    if (i < E) atomicAdd(&g_cnt[dst[i]], 1);
}

// ---------------- launch 2: lookback scan + weight transpose + U table ----
__global__ void scan_prep_kernel(int N, int scanBlocks,
                                 const float* __restrict__ w0a, const float* __restrict__ w0b,
                                 const float* __restrict__ w1a, const float* __restrict__ w1b,
                                 const float* __restrict__ w2a, const float* __restrict__ w2b,
                                 const float* __restrict__ fc1w,
                                 const float* __restrict__ ed, const float* __restrict__ el) {
    const int b = blockIdx.x;
    const int t = threadIdx.x;
    if (b < scanBlocks) {
        // ---- single-pass decoupled-lookback exclusive scan of g_cnt ----
        __shared__ int sm[256];
        __shared__ int s_base;
        int idx = b * 256 + t;
        int v = (idx < N) ? g_cnt[idx] : 0;
        sm[t] = v;
        __syncthreads();
        for (int o = 1; o < 256; o <<= 1) {
            int u = (t >= o) ? sm[t - o] : 0;
            __syncthreads(); sm[t] += u; __syncthreads();
        }
        if (t == 255) {
            int total = sm[255];
            if (b == 0) {
                atomicExch(&g_part[0], 0x80000000u | (unsigned)total);
                s_base = 0;
            } else {
                atomicExch(&g_part[b], 0x40000000u | (unsigned)total);
                int excl = 0;
                for (int p = b - 1;;) {
                    unsigned pv;
                    do { pv = atomicAdd(&g_part[p], 0u); } while (pv < 0x40000000u);
                    excl += (int)(pv & 0x3FFFFFFFu);
                    if (pv >= 0x80000000u) break;
                    p--;
                }
                atomicExch(&g_part[b], 0x80000000u | (unsigned)(excl + total));
                s_base = excl;
            }
        }
        __syncthreads();
        int excl_local = sm[t] - v + s_base;
        if (idx < N) {
            g_rowptr[idx] = excl_local;
            g_cursor[idx] = excl_local;
            if (idx == N - 1) g_rowptr[N] = excl_local + v;
        }
        return;
    }
    // ---- prep region ----
    int j = (b - scanBlocks) * 256 + t;
    if (j < 16384) { int m = j >> 7, k = j & 127; g_wt0a[k * 128 + m] = w0a[j]; return; }
    if ((j -= 16384) < 8192) { int m = j >> 7, k = j & 127; g_wt0b[k * 64 + m] = w0b[j]; return; }
    if ((j -= 8192) < 4096)  { int m = j >> 6, k = j & 63; g_wt1a[k * 64 + m] = w1a[j]; return; }
    if ((j -= 4096) < 4096)  { int m = j >> 6, k = j & 63; g_wt1b[k * 64 + m] = w1b[j]; return; }
    if ((j -= 4096) < 4096)  { int m = j >> 6, k = j & 63; g_wt2a[k * 64 + m] = w2a[j]; return; }
    if ((j -= 4096) < 4096)  { int m = j >> 6, k = j & 63; g_wt2b[k * 64 + m] = w2b[j]; return; }
    if ((j -= 4096) < 20480) { int m = j / 320, k = j - m * 320; g_fc1t[k * 64 + m] = fc1w[j]; return; }
    if ((j -= 20480) < 65536) {
        int c = j >> 6, m = j & 63;
        int d = c >> 4, l = c & 15;
        const float* er = ed + d * 64;
        const float* lr = el + l * 64;
        const float* wr = fc1w + m * 320;
        float s = 0.f;
#pragma unroll 8
        for (int k = 0; k < 64; k++) s = fmaf(er[k], wr[k], s);
#pragma unroll 8
        for (int k = 0; k < 64; k++) s = fmaf(lr[k], wr[64 + k], s);
        g_U[c * 64 + m] = s;
    }
}

// ---------------- launch 3: scatter + re-zero cnt/stats/part ----------------
__global__ void scatter_kernel(const int* __restrict__ src, const int* __restrict__ dst, int E, int N) {
    int i = blockIdx.x * blockDim.x + threadIdx.x;
    if (i < E) {
        int p = atomicAdd(&g_cursor[dst[i]], 1);
        g_srt[p] = src[i];
    }
    if (i < N) g_cnt[i] = 0;
    if (i < 512) g_stats[i] = 0.f;
    if (i < 256) g_part[i] = 0u;
}

// ---------------- launch 4: layer-0 aggregation from L1-resident tables ---
__global__ void agg0_kernel(const float* __restrict__ ed, const float* __restrict__ el,
                            const int* __restrict__ ndeg, const int* __restrict__ nlab,
                            float* __restrict__ hout, int N) {
    int wid  = (blockIdx.x * blockDim.x + threadIdx.x) >> 5;
    int lane = threadIdx.x & 31;
    if (wid >= N) return;
    const float* tbl    = (lane < 16) ? ed : el;
    const int*   idxarr = (lane < 16) ? ndeg : nlab;
    const int    offi   = (lane & 15) * 4;

    float4 acc = *(const float4*)&tbl[idxarr[wid] * 64 + offi];
    int beg = g_rowptr[wid], end = g_rowptr[wid + 1];
    int e = beg;
    for (; e + 8 <= end; e += 8) {
        int s0 = g_srt[e],     s1 = g_srt[e + 1], s2 = g_srt[e + 2], s3 = g_srt[e + 3];
        int s4 = g_srt[e + 4], s5 = g_srt[e + 5], s6 = g_srt[e + 6], s7 = g_srt[e + 7];
        float4 v0 = *(const float4*)&tbl[idxarr[s0] * 64 + offi];
        float4 v1 = *(const float4*)&tbl[idxarr[s1] * 64 + offi];
        float4 v2 = *(const float4*)&tbl[idxarr[s2] * 64 + offi];
        float4 v3 = *(const float4*)&tbl[idxarr[s3] * 64 + offi];
        float4 v4 = *(const float4*)&tbl[idxarr[s4] * 64 + offi];
        float4 v5 = *(const float4*)&tbl[idxarr[s5] * 64 + offi];
        float4 v6 = *(const float4*)&tbl[idxarr[s6] * 64 + offi];
        float4 v7 = *(const float4*)&tbl[idxarr[s7] * 64 + offi];
        acc.x += ((v0.x + v1.x) + (v2.x + v3.x)) + ((v4.x + v5.x) + (v6.x + v7.x));
        acc.y += ((v0.y + v1.y) + (v2.y + v3.y)) + ((v4.y + v5.y) + (v6.y + v7.y));
        acc.z += ((v0.z + v1.z) + (v2.z + v3.z)) + ((v4.z + v5.z) + (v6.z + v7.z));
        acc.w += ((v0.w + v1.w) + (v2.w + v3.w)) + ((v4.w + v5.w) + (v6.w + v7.w));
    }
    for (; e < end; e++) {
        float4 v = *(const float4*)&tbl[idxarr[g_srt[e]] * 64 + offi];
        acc.x += v.x; acc.y += v.y; acc.z += v.z; acc.w += v.w;
    }
    *(float4*)&hout[wid * 128 + lane * 4] = acc;
}

// ---------------- aggregation with fused BN+lrelu of previous layer -------
__global__ void aggbn_kernel(const float* __restrict__ pre,
                             const float* __restrict__ bnw, const float* __restrict__ bnb,
                             float* __restrict__ hout, int N, int bnidx) {
    __shared__ float sc[64], sh[64];
    if (threadIdx.x < 64) {
        int c = threadIdx.x;
        float m   = g_stats[bnidx * 128 + c] / (float)N;
        float var = g_stats[bnidx * 128 + 64 + c] / (float)N - m * m;
        float inv = rsqrtf(var + 1e-5f);
        float a   = bnw[c] * inv;
        sc[c] = a;
        sh[c] = bnb[c] - m * a;
    }
    __syncthreads();
    int wid  = (blockIdx.x * blockDim.x + threadIdx.x) >> 5;
    int lane = threadIdx.x & 31;
    if (wid >= N) return;
    float a0 = sc[lane * 2], a1 = sc[lane * 2 + 1];
    float c0 = sh[lane * 2], c1 = sh[lane * 2 + 1];
#define BNR(v) { v.x = fmaf(v.x, a0, c0); v.x = fmaxf(v.x, 0.01f * v.x); \
                 v.y = fmaf(v.y, a1, c1); v.y = fmaxf(v.y, 0.01f * v.y); }
    float2 acc = *(const float2*)&pre[wid * 64 + lane * 2];
    BNR(acc);
    int beg = g_rowptr[wid], end = g_rowptr[wid + 1];
    int e = beg;
    for (; e + 8 <= end; e += 8) {
        int s0 = g_srt[e],     s1 = g_srt[e + 1], s2 = g_srt[e + 2], s3 = g_srt[e + 3];
        int s4 = g_srt[e + 4], s5 = g_srt[e + 5], s6 = g_srt[e + 6], s7 = g_srt[e + 7];
        float2 v0 = *(const float2*)&pre[s0 * 64 + lane * 2];
        float2 v1 = *(const float2*)&pre[s1 * 64 + lane * 2];
        float2 v2 = *(const float2*)&pre[s2 * 64 + lane * 2];
        float2 v3 = *(const float2*)&pre[s3 * 64 + lane * 2];
        float2 v4 = *(const float2*)&pre[s4 * 64 + lane * 2];
        float2 v5 = *(const float2*)&pre[s5 * 64 + lane * 2];
        float2 v6 = *(const float2*)&pre[s6 * 64 + lane * 2];
        float2 v7 = *(const float2*)&pre[s7 * 64 + lane * 2];
        BNR(v0); BNR(v1); BNR(v2); BNR(v3); BNR(v4); BNR(v5); BNR(v6); BNR(v7);
        acc.x += ((v0.x + v1.x) + (v2.x + v3.x)) + ((v4.x + v5.x) + (v6.x + v7.x));
        acc.y += ((v0.y + v1.y) + (v2.y + v3.y)) + ((v4.y + v5.y) + (v6.y + v7.y));
    }
    for (; e < end; e++) {
        float2 v = *(const float2*)&pre[g_srt[e] * 64 + lane * 2];
        BNR(v);
        acc.x += v.x; acc.y += v.y;
    }
#undef BNR
    *(float2*)&hout[wid * 64 + lane * 2] = acc;
}

// ---------------- GIN MLP: compact weights + pk2, LDS.128 nodes, aliased --
template <int K, int M1>
__global__ void __launch_bounds__(256) mlp_kernel(
    const float* __restrict__ hin,
    const float* __restrict__ wta, const float* __restrict__ ba,
    const float* __restrict__ wtb, const float* __restrict__ bb,
    float* __restrict__ out, int N, int bnidx)
{
    constexpr int TM = M1 / 32;
    constexpr int K4 = K / 4;
    extern __shared__ float smem[];
    float* A_s = smem;                   // K*ASTRIDE (reused for H, M1<=K)
    float* RS  = smem + K * ASTRIDE;     // 512
    float* RQ  = RS + 512;               // 512

    const int tid = threadIdx.x;
    const int n0  = blockIdx.x * 64;

    for (int i = tid; i < 64 * K4; i += 256) {
        int nl = i / K4, k4 = i - nl * K4;
        int n = n0 + nl;
        float4 v = make_float4(0.f, 0.f, 0.f, 0.f);
        if (n < N) v = *(const float4*)&hin[n * K + k4 * 4];
        A_s[(4 * k4 + 0) * ASTRIDE + nl] = v.x;
        A_s[(4 * k4 + 1) * ASTRIDE + nl] = v.y;
        A_s[(4 * k4 + 2) * ASTRIDE + nl] = v.z;
        A_s[(4 * k4 + 3) * ASTRIDE + nl] = v.w;
    }
    __syncthreads();

    const int lane = tid & 31, wrp = tid >> 5;
    const int nb = wrp * 8;

    // ---- GEMM1 ----
    ULL acc[TM][4];
#pragma unroll
    for (int i = 0; i < TM; i++)
#pragma unroll
        for (int p = 0; p < 4; p++) acc[i][p] = 0ULL;

#pragma unroll 8
    for (int k = 0; k < K; k++) {
        const float* row = &A_s[k * ASTRIDE + nb];
        ulonglong2 n01 = *(const ulonglong2*)(row);
        ulonglong2 n23 = *(const ulonglong2*)(row + 4);
        ULL a0 = n01.x, a1 = n01.y, a2 = n23.x, a3 = n23.y;
        if constexpr (TM == 4) {
            float4 w4 = *(const float4*)&wta[k * M1 + lane * 4];
            ULL w0 = pk2(w4.x, w4.x), w1 = pk2(w4.y, w4.y);
            ULL w2 = pk2(w4.z, w4.z), w3 = pk2(w4.w, w4.w);
            fma2(acc[0][0], w0, a0); fma2(acc[0][1], w0, a1); fma2(acc[0][2], w0, a2); fma2(acc[0][3], w0, a3);
            fma2(acc[1][0], w1, a0); fma2(acc[1][1], w1, a1); fma2(acc[1][2], w1, a2); fma2(acc[1][3], w1, a3);
            fma2(acc[2][0], w2, a0); fma2(acc[2][1], w2, a1); fma2(acc[2][2], w2, a2); fma2(acc[2][3], w2, a3);
            fma2(acc[3][0], w3, a0); fma2(acc[3][1], w3, a1); fma2(acc[3][2], w3, a2); fma2(acc[3][3], w3, a3);
        } else {
            float2 wv = *(const float2*)&wta[k * M1 + lane * 2];
            ULL w0 = pk2(wv.x, wv.x), w1 = pk2(wv.y, wv.y);
            fma2(acc[0][0], w0, a0); fma2(acc[0][1], w0, a1); fma2(acc[0][2], w0, a2); fma2(acc[0][3], w0, a3);
            fma2(acc[1][0], w1, a0); fma2(acc[1][1], w1, a1); fma2(acc[1][2], w1, a2); fma2(acc[1][3], w1, a3);
        }
    }

    __syncthreads();   // all A reads done before overwrite with H
#pragma unroll
    for (int i = 0; i < TM; i++) {
        int m = lane * TM + i;
        float bv = ba[m];
#pragma unroll
        for (int p = 0; p < 4; p++) {
            float x, y; upk(acc[i][p], x, y);
            x += bv; y += bv;
            x = fmaxf(x, 0.01f * x); y = fmaxf(y, 0.01f * y);
            *(ULL*)&A_s[m * ASTRIDE + nb + 2 * p] = pk2(x, y);
        }
    }
    __syncthreads();

    // ---- GEMM2 ----
    ULL c2[2][4];
#pragma unroll
    for (int i = 0; i < 2; i++)
#pragma unroll
        for (int p = 0; p < 4; p++) c2[i][p] = 0ULL;
#pragma unroll 8
    for (int k = 0; k < M1; k++) {
        const float* row = &A_s[k * ASTRIDE + nb];
        ulonglong2 n01 = *(const ulonglong2*)(row);
        ulonglong2 n23 = *(const ulonglong2*)(row + 4);
        ULL a0 = n01.x, a1 = n01.y, a2 = n23.x, a3 = n23.y;
        float2 wv = *(const float2*)&wtb[k * 64 + lane * 2];
        ULL w0 = pk2(wv.x, wv.x), w1 = pk2(wv.y, wv.y);
        fma2(c2[0][0], w0, a0); fma2(c2[0][1], w0, a1); fma2(c2[0][2], w0, a2); fma2(c2[0][3], w0, a3);
        fma2(c2[1][0], w1, a0); fma2(c2[1][1], w1, a1); fma2(c2[1][2], w1, a2); fma2(c2[1][3], w1, a3);
    }
    float b0 = bb[lane * 2], b1 = bb[lane * 2 + 1];
    float s0 = 0.f, q0 = 0.f, s1 = 0.f, q1 = 0.f;
#pragma unroll
    for (int p = 0; p < 4; p++) {
        float x0, x1, y0, y1;
        upk(c2[0][p], x0, x1);
        upk(c2[1][p], y0, y1);
        int na = n0 + nb + 2 * p;
        if (na < N) {
            float o0 = x0 + b0, o1 = y0 + b1;
            *(float2*)&out[na * 64 + lane * 2] = make_float2(o0, o1);
            s0 += o0; q0 = fmaf(o0, o0, q0); s1 += o1; q1 = fmaf(o1, o1, q1);
        }
        if (na + 1 < N) {
            float o0 = x1 + b0, o1 = y1 + b1;
            *(float2*)&out[(na + 1) * 64 + lane * 2] = make_float2(o0, o1);
            s0 += o0; q0 = fmaf(o0, o0, q0); s1 += o1; q1 = fmaf(o1, o1, q1);
        }
    }
    RS[wrp * 64 + lane * 2] = s0; RS[wrp * 64 + lane * 2 + 1] = s1;
    RQ[wrp * 64 + lane * 2] = q0; RQ[wrp * 64 + lane * 2 + 1] = q1;
    __syncthreads();
    if (tid < 128) {
        int c = tid & 63;
        const float* P = (tid >= 64) ? RQ : RS;
        float v = 0.f;
#pragma unroll
        for (int w = 0; w < 8; w++) v += P[w * 64 + c];
        atomicAdd(&g_stats[bnidx * 128 + ((tid >= 64) ? 64 : 0) + c], v);
    }
}

// ---------------- fc1 head GEMM (K=192 + U-table), fused BN-in + stats ----
__global__ void __launch_bounds__(256) fc1_kernel(
    const int* __restrict__ ndeg, const int* __restrict__ nlab,
    const float* __restrict__ pre1, const float* __restrict__ pre2, const float* __restrict__ pre3,
    const float* __restrict__ bn0w, const float* __restrict__ bn0b,
    const float* __restrict__ bn1w, const float* __restrict__ bn1b,
    const float* __restrict__ bn2w, const float* __restrict__ bn2b,
    const float* __restrict__ fb,
    float* __restrict__ out, int N)
{
    extern __shared__ float smem[];
    float* A_s = smem;                      // 192*ASTRIDE
    float* RS  = A_s + 192 * ASTRIDE;       // 512
    float* RQ  = RS + 512;                  // 512
    float* sc  = RQ + 512;                  // 192
    float* sh  = sc + 192;                  // 192
    int*   s_comb = (int*)(sh + 192);       // 64

    const int tid = threadIdx.x;
    const int n0 = blockIdx.x * 64;
    if (tid < 192) {
        int l = tid >> 6, c = tid & 63;
        const float* w = (l == 0) ? bn0w : ((l == 1) ? bn1w : bn2w);
        const float* b = (l == 0) ? bn0b : ((l == 1) ? bn1b : bn2b);
        float m   = g_stats[l * 128 + c] / (float)N;
        float var = g_stats[l * 128 + 64 + c] / (float)N - m * m;
        float inv = rsqrtf(var + 1e-5f);
        float a   = w[c] * inv;
        sc[tid] = a;
        sh[tid] = b[c] - m * a;
    }
    if (tid >= 192 && tid < 256) {
        int nl = tid - 192;
        int n = n0 + nl;
        s_comb[nl] = (n < N) ? (ndeg[n] * 16 + nlab[n]) * 64 : 0;
    }
    __syncthreads();

    for (int i = tid; i < 64 * 192; i += 256) {
        int nl = i / 192, k = i - nl * 192;
        int n = n0 + nl;
        float v = 0.f;
        if (n < N) {
            int l = k >> 6, c = k & 63;
            const float* pr = (l == 0) ? pre1 : ((l == 1) ? pre2 : pre3);
            float p = fmaf(pr[n * 64 + c], sc[k], sh[k]);
            v = fmaxf(p, 0.01f * p);
        }
        A_s[k * ASTRIDE + nl] = v;
    }
    __syncthreads();

    const int lane = tid & 31, wrp = tid >> 5;
    const int nb = wrp * 8;

    ULL c2[2][4];
#pragma unroll
    for (int i = 0; i < 2; i++)
#pragma unroll
        for (int p = 0; p < 4; p++) c2[i][p] = 0ULL;

#pragma unroll 8
    for (int k = 0; k < 192; k++) {
        const float* row = &A_s[k * ASTRIDE + nb];
        ulonglong2 n01 = *(const ulonglong2*)(row);
        ulonglong2 n23 = *(const ulonglong2*)(row + 4);
        ULL a0 = n01.x, a1 = n01.y, a2 = n23.x, a3 = n23.y;
        float2 wv = *(const float2*)&g_fc1t[(128 + k) * 64 + lane * 2];
        ULL w0 = pk2(wv.x, wv.x), w1 = pk2(wv.y, wv.y);
        fma2(c2[0][0], w0, a0); fma2(c2[0][1], w0, a1); fma2(c2[0][2], w0, a2); fma2(c2[0][3], w0, a3);
        fma2(c2[1][0], w1, a0); fma2(c2[1][1], w1, a1); fma2(c2[1][2], w1, a2); fma2(c2[1][3], w1, a3);
    }

    float b0 = fb[lane * 2], b1 = fb[lane * 2 + 1];
    float s0 = 0.f, q0 = 0.f, s1 = 0.f, q1 = 0.f;
#pragma unroll
    for (int p = 0; p < 4; p++) {
        float x0, x1, y0, y1;
        upk(c2[0][p], x0, x1);
        upk(c2[1][p], y0, y1);
        int na = n0 + nb + 2 * p;
        if (na < N) {
            float2 uv = *(const float2*)&g_U[s_comb[nb + 2 * p] + lane * 2];
            float o0 = x0 + b0 + uv.x, o1 = y0 + b1 + uv.y;
            *(float2*)&out[na * 64 + lane * 2] = make_float2(o0, o1);
            s0 += o0; q0 = fmaf(o0, o0, q0); s1 += o1; q1 = fmaf(o1, o1, q1);
        }
        if (na + 1 < N) {
            float2 uv = *(const float2*)&g_U[s_comb[nb + 2 * p + 1] + lane * 2];
            float o0 = x1 + b0 + uv.x, o1 = y1 + b1 + uv.y;
            *(float2*)&out[(na + 1) * 64 + lane * 2] = make_float2(o0, o1);
            s0 += o0; q0 = fmaf(o0, o0, q0); s1 += o1; q1 = fmaf(o1, o1, q1);
        }
    }
    RS[wrp * 64 + lane * 2] = s0; RS[wrp * 64 + lane * 2 + 1] = s1;
    RQ[wrp * 64 + lane * 2] = q0; RQ[wrp * 64 + lane * 2 + 1] = q1;
    __syncthreads();
    if (tid < 128) {
        int c = tid & 63;
        const float* P = (tid >= 64) ? RQ : RS;
        float v = 0.f;
#pragma unroll
        for (int w = 0; w < 8; w++) v += P[w * 64 + c];
        atomicAdd(&g_stats[3 * 128 + ((tid >= 64) ? 64 : 0) + c], v);
    }
}

// ---------------- final head ----------------
__global__ void final_kernel(const float* __restrict__ hpre,
                             const float* __restrict__ bnw, const float* __restrict__ bnb,
                             const float* __restrict__ fc2w, const float* __restrict__ fc2b,
                             float* __restrict__ out, int N) {
    __shared__ float sc[64], sh[64], w2s[64];
    if (threadIdx.x < 64) {
        int c = threadIdx.x;
        float m   = g_stats[3 * 128 + c] / (float)N;
        float var = g_stats[3 * 128 + 64 + c] / (float)N - m * m;
        float inv = rsqrtf(var + 1e-5f);
        float a   = bnw[c] * inv;
        sc[c]  = a;
        sh[c]  = bnb[c] - m * a;
        w2s[c] = fc2w[c];
    }
    __syncthreads();
    int wid  = (blockIdx.x * blockDim.x + threadIdx.x) >> 5;
    int lane = threadIdx.x & 31;
    if (wid >= N) return;
    float2 v = *(const float2*)&hpre[wid * 64 + lane * 2];
    float x = fmaf(v.x, sc[lane * 2], sh[lane * 2]);         x = fmaxf(x, 0.01f * x);
    float y = fmaf(v.y, sc[lane * 2 + 1], sh[lane * 2 + 1]); y = fmaxf(y, 0.01f * y);
    float acc = fmaf(x, w2s[lane * 2], y * w2s[lane * 2 + 1]);
#pragma unroll
    for (int off = 16; off; off >>= 1) acc += __shfl_xor_sync(0xffffffffu, acc, off);
    if (lane == 0) out[wid] = 1.f / (1.f + expf(-(acc + fc2b[0])));
}

// ---------------- launch ----------------
extern "C" void kernel_launch(void* const* d_in, const int* in_sizes, int n_in,
                              void* d_out, int out_size) {
    const float* emb_deg = (const float*)d_in[0];
    const float* emb_lab = (const float*)d_in[1];
    const float* w0a = (const float*)d_in[2];  const float* b0a = (const float*)d_in[3];
    const float* w0b = (const float*)d_in[4];  const float* b0b = (const float*)d_in[5];
    const float* bn0w = (const float*)d_in[6]; const float* bn0b = (const float*)d_in[7];
    const float* w1a = (const float*)d_in[8];  const float* b1a = (const float*)d_in[9];
    const float* w1b = (const float*)d_in[10]; const float* b1b = (const float*)d_in[11];
    const float* bn1w = (const float*)d_in[12]; const float* bn1b = (const float*)d_in[13];
    const float* w2a = (const float*)d_in[14]; const float* b2a = (const float*)d_in[15];
    const float* w2b = (const float*)d_in[16]; const float* b2b = (const float*)d_in[17];
    const float* bn2w = (const float*)d_in[18]; const float* bn2b = (const float*)d_in[19];
    const float* fc1w = (const float*)d_in[20]; const float* fc1b = (const float*)d_in[21];
    const float* fcbnw = (const float*)d_in[22]; const float* fcbnb = (const float*)d_in[23];
    const float* fc2w = (const float*)d_in[24]; const float* fc2b = (const float*)d_in[25];
    const int* node_deg = (const int*)d_in[26];
    const int* node_lab = (const int*)d_in[27];
    const int* edge = (const int*)d_in[28];

    const int N = in_sizes[26];
    const int E = in_sizes[28] / 2;
    const int* src  = edge;
    const int* dstp = edge + E;
    float* out = (float*)d_out;

    float *hin, *pre1, *pre2, *pre3, *pre4;
    float *wt0a, *wt0b, *wt1a, *wt1b, *wt2a, *wt2b;
    cudaGetSymbolAddress((void**)&hin,  g_hin);
    cudaGetSymbolAddress((void**)&pre1, g_pre1);
    cudaGetSymbolAddress((void**)&pre2, g_pre2);
    cudaGetSymbolAddress((void**)&pre3, g_pre3);
    cudaGetSymbolAddress((void**)&pre4, g_pre4);
    cudaGetSymbolAddress((void**)&wt0a, g_wt0a);
    cudaGetSymbolAddress((void**)&wt0b, g_wt0b);
    cudaGetSymbolAddress((void**)&wt1a, g_wt1a);
    cudaGetSymbolAddress((void**)&wt1b, g_wt1b);
    cudaGetSymbolAddress((void**)&wt2a, g_wt2a);
    cudaGetSymbolAddress((void**)&wt2b, g_wt2b);

    const int TB = 256;
    const int mlpBlocks  = (N + 63) / 64;
    const int warpBlocks = (N * 32 + TB - 1) / TB;
    const int scanBlocks = (N + 255) / 256;
    const int prepBlocks = (61440 + 65536 + 255) / 256;

    const int SM_MLP0 = (128 * ASTRIDE + 1024) * 4;                  // 38912
    const int SM_MLP1 = (64 * ASTRIDE + 1024) * 4;                   // 21504
    const int SM_FC1  = (192 * ASTRIDE + 1024 + 384 + 64) * 4;       // 58112
    cudaFuncSetAttribute(mlp_kernel<128, 128>, cudaFuncAttributeMaxDynamicSharedMemorySize, SM_MLP0);
    cudaFuncSetAttribute(mlp_kernel<64, 64>,   cudaFuncAttributeMaxDynamicSharedMemorySize, SM_MLP1);
    cudaFuncSetAttribute(fc1_kernel,           cudaFuncAttributeMaxDynamicSharedMemorySize, SM_FC1);

    // 1: histogram (g_cnt zero: static-init first call, re-zeroed by scatter)
    hist_kernel<<<(E + TB - 1) / TB, TB>>>(dstp, E);
    // 2: lookback scan + weight transpose + U table (scan blocks first in blockIdx order)
    scan_prep_kernel<<<scanBlocks + prepBlocks, 256>>>(N, scanBlocks,
                                                       w0a, w0b, w1a, w1b, w2a, w2b,
                                                       fc1w, emb_deg, emb_lab);
    // 3: scatter + re-zero cnt/stats/part
    scatter_kernel<<<(E + TB - 1) / TB, TB>>>(src, dstp, E, N);

    // 4-5: layer 0
    agg0_kernel<<<warpBlocks, TB>>>(emb_deg, emb_lab, node_deg, node_lab, hin, N);
    mlp_kernel<128, 128><<<mlpBlocks, 256, SM_MLP0>>>(hin, wt0a, b0a, wt0b, b0b, pre1, N, 0);

    // 6-7: layer 1
    aggbn_kernel<<<warpBlocks, TB>>>(pre1, bn0w, bn0b, hin, N, 0);
    mlp_kernel<64, 64><<<mlpBlocks, 256, SM_MLP1>>>(hin, wt1a, b1a, wt1b, b1b, pre2, N, 1);

    // 8-9: layer 2
    aggbn_kernel<<<warpBlocks, TB>>>(pre2, bn1w, bn1b, hin, N, 1);
    mlp_kernel<64, 64><<<mlpBlocks, 256, SM_MLP1>>>(hin, wt2a, b2a, wt2b, b2b, pre3, N, 2);

    // 10-11: head (fc1 uses precomputed U for the x0 block)
    fc1_kernel<<<mlpBlocks, 256, SM_FC1>>>(node_deg, node_lab,
                                           pre1, pre2, pre3,
                                           bn0w, bn0b, bn1w, bn1b, bn2w, bn2b,
                                           fc1b, pre4, N);
    final_kernel<<<warpBlocks, TB>>>(pre4, fcbnw, fcbnb, fc2w, fc2b, out, N);
}